// round 13
// baseline (speedup 1.0000x reference)
#include <cuda_runtime.h>
#include <cuda_fp16.h>
#include <math.h>
#include <stdint.h>

#define B_    2
#define N_    1024
#define D_    1024
#define H_    16
#define DH_   64
#define MLP_  4096
#define DEPTH_ 6
#define M_    (B_ * N_)   /* 2048 rows */

// ---------------- scratch -----------------------------------------------
__device__ __half g_h  [(size_t)M_ * D_];
__device__ __half g_qkv[(size_t)M_ * 3 * D_];
__device__ __half g_vt [(size_t)B_ * H_ * DH_ * N_];
__device__ __half g_o  [(size_t)M_ * D_];
__device__ __half g_mlp[(size_t)M_ * MLP_];
__device__ __half g_wqkv[(size_t)DEPTH_ * D_ * 3 * D_];
__device__ __half g_wout[(size_t)DEPTH_ * D_ * D_];
__device__ __half g_w1  [(size_t)DEPTH_ * D_ * MLP_];
__device__ __half g_w2  [(size_t)DEPTH_ * MLP_ * D_];

// ---------------- helpers ---------------------------------------------------
__device__ __forceinline__ void mma16(float* d, const uint32_t* a, const uint32_t* b) {
    asm volatile(
        "mma.sync.aligned.m16n8k16.row.col.f32.f16.f16.f32 "
        "{%0,%1,%2,%3},{%4,%5,%6,%7},{%8,%9},{%0,%1,%2,%3};"
        : "+f"(d[0]), "+f"(d[1]), "+f"(d[2]), "+f"(d[3])
        : "r"(a[0]), "r"(a[1]), "r"(a[2]), "r"(a[3]),
          "r"(b[0]), "r"(b[1]));
}
__device__ __forceinline__ void cp16(void* smem_dst, const void* gmem_src) {
    uint32_t dst = (uint32_t)__cvta_generic_to_shared(smem_dst);
    asm volatile("cp.async.cg.shared.global [%0], [%1], 16;"
                 :: "r"(dst), "l"(gmem_src));
}
__device__ __forceinline__ void cp_commit() {
    asm volatile("cp.async.commit_group;");
}

// ---------------- weight pre-pass: [K,N] fp32 -> [N,K] fp16 -----------------
__global__ void __launch_bounds__(256) wtrans_kernel(
    const float* __restrict__ src, __half* __restrict__ dst, int K, int N)
{
    __shared__ float t[32][33];
    int n0 = blockIdx.x * 32, k0 = blockIdx.y * 32;
    src += (size_t)blockIdx.z * K * N;
    dst += (size_t)blockIdx.z * K * N;
    int tx = threadIdx.x & 31, ty = threadIdx.x >> 5;
#pragma unroll
    for (int i = ty; i < 32; i += 8)
        t[i][tx] = src[(size_t)(k0 + i) * N + n0 + tx];
    __syncthreads();
#pragma unroll
    for (int i = ty; i < 32; i += 8)
        dst[(size_t)(n0 + i) * K + k0 + tx] = __float2half_rn(t[tx][i]);
}

// ---------------- V transpose: qkv fp16 -> Vt[bh][d][j] ---------------------
__global__ void __launch_bounds__(256) vtrans_kernel(
    const __half* __restrict__ qkv, __half* __restrict__ vt)
{
    __shared__ __half t[64][66];
    int bh = blockIdx.y;
    int b = bh >> 4, h = bh & 15;
    int j0 = blockIdx.x * 64;
    const __half* src = qkv + (size_t)b * N_ * 3 * D_ + 2 * D_ + (size_t)h * DH_;
    __half* dst = vt + (size_t)bh * DH_ * N_;
    int tid = threadIdx.x;
#pragma unroll
    for (int i = 0; i < 16; i++) {
        int idx = tid + i * 256;
        int j = idx >> 6, d = idx & 63;
        t[j][d] = src[(size_t)(j0 + j) * 3 * D_ + d];
    }
    __syncthreads();
#pragma unroll
    for (int i = 0; i < 16; i++) {
        int idx = tid + i * 256;
        int d = idx >> 6, j = idx & 63;
        dst[(size_t)d * N_ + j0 + j] = t[j][d];
    }
}

// ---------------- LayerNorm (emits fp16) -----------------------------------
__global__ void __launch_bounds__(256) ln_kernel(
    const float* __restrict__ x, const float* __restrict__ s,
    const float* __restrict__ b, __half* __restrict__ o)
{
    __shared__ float red[2][8];
    int row = blockIdx.x;
    const float* xr = x + (size_t)row * D_;
    __half* orow = o + (size_t)row * D_;
    int t = threadIdx.x;
    float v[4];
    float sum = 0.f, sq = 0.f;
#pragma unroll
    for (int i = 0; i < 4; i++) {
        float z = xr[t + i * 256];
        v[i] = z; sum += z; sq += z * z;
    }
#pragma unroll
    for (int off = 16; off > 0; off >>= 1) {
        sum += __shfl_xor_sync(0xffffffffu, sum, off);
        sq  += __shfl_xor_sync(0xffffffffu, sq,  off);
    }
    if ((t & 31) == 0) { red[0][t >> 5] = sum; red[1][t >> 5] = sq; }
    __syncthreads();
    sum = 0.f; sq = 0.f;
#pragma unroll
    for (int i = 0; i < 8; i++) { sum += red[0][i]; sq += red[1][i]; }
    float mean = sum * (1.f / D_);
    float var  = sq  * (1.f / D_) - mean * mean;
    float rstd = rsqrtf(var + 1e-5f);
#pragma unroll
    for (int i = 0; i < 4; i++) {
        int c = t + i * 256;
        orow[c] = __float2half_rn((v[i] - mean) * rstd * s[c] + b[c]);
    }
}

// ---------------- fp16 tensor-core GEMM, cp.async, templated BM -------------
// A: [M][K] fp16. Wt: [N][K] fp16. Tile BM x 128, BK=64, 256 thr (8 warps,
// 4m x 2n, warp tile (BM/4) x 64). EPI bit0:+bias bit1:gelu bit2:+res.
template<int BM_, int EPI, int OH>
__global__ void __launch_bounds__(256, 2) gemm_hf(
    const __half* __restrict__ A, const __half* __restrict__ Wt,
    const float* __restrict__ bias, const float* __restrict__ res,
    void* __restrict__ Cv, int M, int N, int K)
{
    const int MI = BM_ / 64, NI = 8;     // WM = BM_/4, WN = 64
    const int WM = BM_ / 4;
    const int RS = 144;
    const int A_BYTES = BM_ * RS;
    const int B_BYTES = 128 * RS;

    extern __shared__ char sm[];
    char* Asm = sm;
    char* Bsm = sm + 2 * A_BYTES;

    int tid = threadIdx.x;
    int bx = blockIdx.x, by = blockIdx.y;
    int wid = tid >> 5, lane = tid & 31;
    int wn = wid & 1, wm = wid >> 1;
    int g = lane >> 2, q = lane & 3;

    const __half* Ab = A  + (size_t)by * BM_ * K;
    const __half* Bb = Wt + (size_t)bx * 128 * K;
    int KT = K / 64;

    float acc[MI][NI][4];
#pragma unroll
    for (int mi = 0; mi < MI; mi++)
#pragma unroll
        for (int ni = 0; ni < NI; ni++)
#pragma unroll
            for (int k = 0; k < 4; k++) acc[mi][ni][k] = 0.f;

    auto load_tile = [&](int kt, int s) {
#pragma unroll
        for (int i = 0; i < BM_ / 32; i++) {
            int idx = tid + i * 256;
            int r = idx >> 3, c = idx & 7;
            cp16(Asm + s * A_BYTES + r * RS + c * 16,
                 Ab + (size_t)r * K + kt * 64 + c * 8);
        }
#pragma unroll
        for (int i = 0; i < 4; i++) {
            int idx = tid + i * 256;
            int r = idx >> 3, c = idx & 7;
            cp16(Bsm + s * B_BYTES + r * RS + c * 16,
                 Bb + (size_t)r * K + kt * 64 + c * 8);
        }
        cp_commit();
    };

    load_tile(0, 0);

    for (int kt = 0; kt < KT; kt++) {
        int s = kt & 1;
        if (kt + 1 < KT) {
            load_tile(kt + 1, (kt + 1) & 1);
            asm volatile("cp.async.wait_group 1;");
        } else {
            asm volatile("cp.async.wait_group 0;");
        }
        __syncthreads();
        const char* As = Asm + s * A_BYTES;
        const char* Bs = Bsm + s * B_BYTES;
#pragma unroll
        for (int ks = 0; ks < 4; ks++) {
            int kb = ks * 32;
            uint32_t a[MI][4];
#pragma unroll
            for (int mi = 0; mi < MI; mi++) {
                const char* p0 = As + (wm * WM + mi * 16 + g) * RS + kb + 4 * q;
                const char* p1 = As + (wm * WM + mi * 16 + 8 + g) * RS + kb + 4 * q;
                a[mi][0] = *(const uint32_t*)(p0);
                a[mi][1] = *(const uint32_t*)(p1);
                a[mi][2] = *(const uint32_t*)(p0 + 16);
                a[mi][3] = *(const uint32_t*)(p1 + 16);
            }
            uint32_t b[NI][2];
#pragma unroll
            for (int ni = 0; ni < NI; ni++) {
                const char* pb = Bs + (wn * 64 + ni * 8 + g) * RS + kb + 4 * q;
                b[ni][0] = *(const uint32_t*)(pb);
                b[ni][1] = *(const uint32_t*)(pb + 16);
            }
#pragma unroll
            for (int mi = 0; mi < MI; mi++)
#pragma unroll
                for (int ni = 0; ni < NI; ni++) mma16(acc[mi][ni], a[mi], b[ni]);
        }
        __syncthreads();
    }

#pragma unroll
    for (int mi = 0; mi < MI; mi++) {
        int r0 = by * BM_ + wm * WM + mi * 16 + g;
#pragma unroll
        for (int ni = 0; ni < NI; ni++) {
            int c = bx * 128 + wn * 64 + ni * 8 + q * 2;
            float2 v0 = make_float2(acc[mi][ni][0], acc[mi][ni][1]);
            float2 v1 = make_float2(acc[mi][ni][2], acc[mi][ni][3]);
            if (EPI & 1) {
                float b0 = bias[c], b1 = bias[c + 1];
                v0.x += b0; v0.y += b1; v1.x += b0; v1.y += b1;
            }
            if (EPI & 2) {
                const float is2 = 0.70710678118654752f;
                v0.x = 0.5f * v0.x * (1.f + erff(v0.x * is2));
                v0.y = 0.5f * v0.y * (1.f + erff(v0.y * is2));
                v1.x = 0.5f * v1.x * (1.f + erff(v1.x * is2));
                v1.y = 0.5f * v1.y * (1.f + erff(v1.y * is2));
            }
            size_t a0 = (size_t)r0 * N + c;
            size_t a1 = (size_t)(r0 + 8) * N + c;
            if (EPI & 4) {
                float2 r0v = *(const float2*)(res + a0);
                float2 r1v = *(const float2*)(res + a1);
                v0.x += r0v.x; v0.y += r0v.y; v1.x += r1v.x; v1.y += r1v.y;
            }
            if (OH) {
                __half* C = (__half*)Cv;
                *(__half2*)(C + a0) = __floats2half2_rn(v0.x, v0.y);
                *(__half2*)(C + a1) = __floats2half2_rn(v1.x, v1.y);
            } else {
                float* C = (float*)Cv;
                *(float2*)(C + a0) = v0;
                *(float2*)(C + a1) = v1;
            }
        }
    }
}

// ---------------- fused flash attention (fp16) ------------------------------
#define FL_RS    144
#define FL_Q     0
#define FL_K     (128 * FL_RS)
#define FL_V     (FL_K + 2 * 64 * FL_RS)
#define FL_P     (FL_V + 2 * 64 * FL_RS)
#define FL_SMEM  (FL_P + 8 * 16 * FL_RS)    /* 73728 */

__global__ void __launch_bounds__(256, 2) flash_hf(
    const __half* __restrict__ qkv, const __half* __restrict__ vt,
    __half* __restrict__ o)
{
    const int RS = FL_RS;
    extern __shared__ char sm[];
    char* Qs = sm + FL_Q;
    char* Ks = sm + FL_K;
    char* Vs = sm + FL_V;

    int bh = blockIdx.y;
    int b = bh >> 4, h = bh & 15;
    int i0 = blockIdx.x * 128;
    const __half* Qb  = qkv + (size_t)b * N_ * 3 * D_ + (size_t)h * DH_;
    const __half* Kb  = Qb + D_;
    const __half* Vtb = vt + (size_t)bh * DH_ * N_;

    int tid = threadIdx.x, wid = tid >> 5, lane = tid & 31;
    int g = lane >> 2, q = lane & 3;
    char* Pw = sm + FL_P + wid * 16 * RS;

#pragma unroll
    for (int i = 0; i < 4; i++) {
        int idx = tid + i * 256;
        int r = idx >> 3, c = idx & 7;
        cp16(Qs + r * RS + c * 16, Qb + (size_t)(i0 + r) * 3 * D_ + c * 8);
    }
    cp_commit();

    auto load_kv = [&](int kt, int s) {
        int j0 = kt * 64;
#pragma unroll
        for (int i = 0; i < 2; i++) {
            int idx = tid + i * 256;
            int r = idx >> 3, c = idx & 7;
            cp16(Ks + s * 64 * RS + r * RS + c * 16,
                 Kb + (size_t)(j0 + r) * 3 * D_ + c * 8);
            cp16(Vs + s * 64 * RS + r * RS + c * 16,
                 Vtb + (size_t)r * N_ + j0 + c * 8);
        }
        cp_commit();
    };

    load_kv(0, 0);

    float oacc[8][4];
#pragma unroll
    for (int ni = 0; ni < 8; ni++)
#pragma unroll
        for (int k = 0; k < 4; k++) oacc[ni][k] = 0.f;
    float mr0 = -1e30f, mr1 = -1e30f, lr0 = 0.f, lr1 = 0.f;

    const float scale = 0.03125f;
    char* Qw = Qs + wid * 16 * RS;

    for (int kt = 0; kt < 16; kt++) {
        int s = kt & 1;
        if (kt + 1 < 16) {
            load_kv(kt + 1, (kt + 1) & 1);
            asm volatile("cp.async.wait_group 1;");
        } else {
            asm volatile("cp.async.wait_group 0;");
        }
        __syncthreads();
        const char* Kc = Ks + s * 64 * RS;
        const char* Vc = Vs + s * 64 * RS;

        float sacc[8][4];
#pragma unroll
        for (int ni = 0; ni < 8; ni++)
#pragma unroll
            for (int k = 0; k < 4; k++) sacc[ni][k] = 0.f;
#pragma unroll
        for (int ks = 0; ks < 4; ks++) {
            int kb = ks * 32;
            uint32_t a[4];
            const char* p0 = Qw + g * RS + kb + 4 * q;
            const char* p1 = Qw + (8 + g) * RS + kb + 4 * q;
            a[0] = *(const uint32_t*)(p0);
            a[1] = *(const uint32_t*)(p1);
            a[2] = *(const uint32_t*)(p0 + 16);
            a[3] = *(const uint32_t*)(p1 + 16);
#pragma unroll
            for (int ni = 0; ni < 8; ni++) {
                uint32_t b2[2];
                const char* pb = Kc + (ni * 8 + g) * RS + kb + 4 * q;
                b2[0] = *(const uint32_t*)(pb);
                b2[1] = *(const uint32_t*)(pb + 16);
                mma16(sacc[ni], a, b2);
            }
        }

        float mx0 = -1e30f, mx1 = -1e30f;
#pragma unroll
        for (int ni = 0; ni < 8; ni++) {
            sacc[ni][0] *= scale; sacc[ni][1] *= scale;
            sacc[ni][2] *= scale; sacc[ni][3] *= scale;
            mx0 = fmaxf(mx0, fmaxf(sacc[ni][0], sacc[ni][1]));
            mx1 = fmaxf(mx1, fmaxf(sacc[ni][2], sacc[ni][3]));
        }
        mx0 = fmaxf(mx0, __shfl_xor_sync(0xffffffffu, mx0, 1));
        mx0 = fmaxf(mx0, __shfl_xor_sync(0xffffffffu, mx0, 2));
        mx1 = fmaxf(mx1, __shfl_xor_sync(0xffffffffu, mx1, 1));
        mx1 = fmaxf(mx1, __shfl_xor_sync(0xffffffffu, mx1, 2));
        float mn0 = fmaxf(mr0, mx0), mn1 = fmaxf(mr1, mx1);
        float corr0 = __expf(mr0 - mn0), corr1 = __expf(mr1 - mn1);
        mr0 = mn0; mr1 = mn1;

        float ls0 = 0.f, ls1 = 0.f;
#pragma unroll
        for (int ni = 0; ni < 8; ni++) {
            float p0 = __expf(sacc[ni][0] - mn0);
            float p1 = __expf(sacc[ni][1] - mn0);
            float p2 = __expf(sacc[ni][2] - mn1);
            float p3 = __expf(sacc[ni][3] - mn1);
            ls0 += p0 + p1; ls1 += p2 + p3;
            int cb = ni * 16 + 4 * q;
            *(__half2*)(Pw + g * RS + cb)       = __floats2half2_rn(p0, p1);
            *(__half2*)(Pw + (8 + g) * RS + cb) = __floats2half2_rn(p2, p3);
        }
        lr0 = lr0 * corr0 + ls0;
        lr1 = lr1 * corr1 + ls1;
#pragma unroll
        for (int ni = 0; ni < 8; ni++) {
            oacc[ni][0] *= corr0; oacc[ni][1] *= corr0;
            oacc[ni][2] *= corr1; oacc[ni][3] *= corr1;
        }
        __syncwarp();

#pragma unroll
        for (int ks = 0; ks < 4; ks++) {
            int kb = ks * 32;
            uint32_t a[4];
            const char* p0 = Pw + g * RS + kb + 4 * q;
            const char* p1 = Pw + (8 + g) * RS + kb + 4 * q;
            a[0] = *(const uint32_t*)(p0);
            a[1] = *(const uint32_t*)(p1);
            a[2] = *(const uint32_t*)(p0 + 16);
            a[3] = *(const uint32_t*)(p1 + 16);
#pragma unroll
            for (int ni = 0; ni < 8; ni++) {
                uint32_t b2[2];
                const char* pb = Vc + (ni * 8 + g) * RS + kb + 4 * q;
                b2[0] = *(const uint32_t*)(pb);
                b2[1] = *(const uint32_t*)(pb + 16);
                mma16(oacc[ni], a, b2);
            }
        }
        __syncthreads();
    }

    lr0 += __shfl_xor_sync(0xffffffffu, lr0, 1);
    lr0 += __shfl_xor_sync(0xffffffffu, lr0, 2);
    lr1 += __shfl_xor_sync(0xffffffffu, lr1, 1);
    lr1 += __shfl_xor_sync(0xffffffffu, lr1, 2);
    float inv0 = 1.f / lr0, inv1 = 1.f / lr1;

    int r0 = i0 + wid * 16 + g, r1 = r0 + 8;
#pragma unroll
    for (int ni = 0; ni < 8; ni++) {
        int c = h * DH_ + ni * 8 + q * 2;
        size_t a0 = ((size_t)b * N_ + r0) * D_ + c;
        size_t a1 = ((size_t)b * N_ + r1) * D_ + c;
        *(__half2*)(o + a0) = __floats2half2_rn(oacc[ni][0] * inv0, oacc[ni][1] * inv0);
        *(__half2*)(o + a1) = __floats2half2_rn(oacc[ni][2] * inv1, oacc[ni][3] * inv1);
    }
}

// ---------------- orchestration --------------------------------------------
#define HF_SMEM128 (2 * (128 * 144) + 2 * (128 * 144))   /* 73728 */
#define HF_SMEM64  (2 * (64 * 144) + 2 * (128 * 144))    /* 55296 */

extern "C" void kernel_launch(void* const* d_in, const int* in_sizes, int n_in,
                              void* d_out, int out_size)
{
    (void)in_sizes; (void)n_in; (void)out_size;
    const float* x     = (const float*)d_in[0];
    const float* ln1_s = (const float*)d_in[1];
    const float* ln1_b = (const float*)d_in[2];
    const float* w_qkv = (const float*)d_in[3];
    const float* w_out = (const float*)d_in[4];
    const float* b_out = (const float*)d_in[5];
    const float* ln2_s = (const float*)d_in[6];
    const float* ln2_b = (const float*)d_in[7];
    const float* w1    = (const float*)d_in[8];
    const float* b1    = (const float*)d_in[9];
    const float* w2    = (const float*)d_in[10];
    const float* b2    = (const float*)d_in[11];
    float* out = (float*)d_out;

    __half *h, *qkv, *vt, *o, *mlp, *wqkv, *wout, *w1t, *w2t;
    cudaGetSymbolAddress((void**)&h,    g_h);
    cudaGetSymbolAddress((void**)&qkv,  g_qkv);
    cudaGetSymbolAddress((void**)&vt,   g_vt);
    cudaGetSymbolAddress((void**)&o,    g_o);
    cudaGetSymbolAddress((void**)&mlp,  g_mlp);
    cudaGetSymbolAddress((void**)&wqkv, g_wqkv);
    cudaGetSymbolAddress((void**)&wout, g_wout);
    cudaGetSymbolAddress((void**)&w1t,  g_w1);
    cudaGetSymbolAddress((void**)&w2t,  g_w2);

    cudaFuncSetAttribute(gemm_hf<128, 0, 1>,
        cudaFuncAttributeMaxDynamicSharedMemorySize, HF_SMEM128);
    cudaFuncSetAttribute(gemm_hf<128, 3, 1>,
        cudaFuncAttributeMaxDynamicSharedMemorySize, HF_SMEM128);
    cudaFuncSetAttribute(gemm_hf<64, 5, 0>,
        cudaFuncAttributeMaxDynamicSharedMemorySize, HF_SMEM64);
    cudaFuncSetAttribute(flash_hf,
        cudaFuncAttributeMaxDynamicSharedMemorySize, FL_SMEM);

    // pre-pass: weights -> [N][K] fp16
    wtrans_kernel<<<dim3(3 * D_ / 32, D_ / 32, DEPTH_), 256>>>(w_qkv, wqkv, D_, 3 * D_);
    wtrans_kernel<<<dim3(D_ / 32, D_ / 32, DEPTH_), 256>>>(w_out, wout, D_, D_);
    wtrans_kernel<<<dim3(MLP_ / 32, D_ / 32, DEPTH_), 256>>>(w1, w1t, D_, MLP_);
    wtrans_kernel<<<dim3(D_ / 32, MLP_ / 32, DEPTH_), 256>>>(w2, w2t, MLP_, D_);

    cudaMemcpyAsync(out, x, (size_t)M_ * D_ * sizeof(float),
                    cudaMemcpyDeviceToDevice);

    for (int l = 0; l < DEPTH_; l++) {
        // --- attention block ---
        ln_kernel<<<M_, 256>>>(out, ln1_s + (size_t)l * D_, ln1_b + (size_t)l * D_, h);
        gemm_hf<128, 0, 1><<<dim3(3 * D_ / 128, M_ / 128), 256, HF_SMEM128>>>(
            h, wqkv + (size_t)l * D_ * 3 * D_, nullptr, nullptr,
            qkv, M_, 3 * D_, D_);
        vtrans_kernel<<<dim3(N_ / 64, B_ * H_), 256>>>(qkv, vt);
        flash_hf<<<dim3(N_ / 128, B_ * H_), 256, FL_SMEM>>>(qkv, vt, o);
        gemm_hf<64, 5, 0><<<dim3(D_ / 128, M_ / 64), 256, HF_SMEM64>>>(
            o, wout + (size_t)l * D_ * D_, b_out + (size_t)l * D_,
            out, out, M_, D_, D_);
        // --- MLP block ---
        ln_kernel<<<M_, 256>>>(out, ln2_s + (size_t)l * D_, ln2_b + (size_t)l * D_, h);
        gemm_hf<128, 3, 1><<<dim3(MLP_ / 128, M_ / 128), 256, HF_SMEM128>>>(
            h, w1t + (size_t)l * D_ * MLP_, b1 + (size_t)l * MLP_,
            nullptr, mlp, M_, MLP_, D_);
        gemm_hf<64, 5, 0><<<dim3(D_ / 128, M_ / 64), 256, HF_SMEM64>>>(
            mlp, w2t + (size_t)l * MLP_ * D_, b2 + (size_t)l * D_,
            out, out, M_, D_, MLP_);
    }
}

// round 14
// speedup vs baseline: 1.0706x; 1.0706x over previous
#include <cuda_runtime.h>
#include <cuda_fp16.h>
#include <math.h>
#include <stdint.h>

#define B_    2
#define N_    1024
#define D_    1024
#define H_    16
#define DH_   64
#define MLP_  4096
#define DEPTH_ 6
#define M_    (B_ * N_)   /* 2048 rows */

// ---------------- scratch -----------------------------------------------
__device__ __half g_h  [(size_t)M_ * D_];
__device__ __half g_qkv[(size_t)M_ * 3 * D_];
__device__ __half g_vt [(size_t)B_ * H_ * DH_ * N_];
__device__ __half g_o  [(size_t)M_ * D_];
__device__ __half g_mlp[(size_t)M_ * MLP_];
__device__ float  g_part[2 * (size_t)M_ * D_];      // split-K partials (16MB)
__device__ __half g_wqkv[(size_t)DEPTH_ * D_ * 3 * D_];
__device__ __half g_wout[(size_t)DEPTH_ * D_ * D_];
__device__ __half g_w1  [(size_t)DEPTH_ * D_ * MLP_];
__device__ __half g_w2  [(size_t)DEPTH_ * MLP_ * D_];

// ---------------- helpers ---------------------------------------------------
__device__ __forceinline__ void mma16(float* d, const uint32_t* a, const uint32_t* b) {
    asm volatile(
        "mma.sync.aligned.m16n8k16.row.col.f32.f16.f16.f32 "
        "{%0,%1,%2,%3},{%4,%5,%6,%7},{%8,%9},{%0,%1,%2,%3};"
        : "+f"(d[0]), "+f"(d[1]), "+f"(d[2]), "+f"(d[3])
        : "r"(a[0]), "r"(a[1]), "r"(a[2]), "r"(a[3]),
          "r"(b[0]), "r"(b[1]));
}
__device__ __forceinline__ void cp16(void* smem_dst, const void* gmem_src) {
    uint32_t dst = (uint32_t)__cvta_generic_to_shared(smem_dst);
    asm volatile("cp.async.cg.shared.global [%0], [%1], 16;"
                 :: "r"(dst), "l"(gmem_src));
}
__device__ __forceinline__ void cp_commit() {
    asm volatile("cp.async.commit_group;");
}

// ---------------- weight pre-pass: [K,N] fp32 -> [N,K] fp16 -----------------
__global__ void __launch_bounds__(256) wtrans_kernel(
    const float* __restrict__ src, __half* __restrict__ dst, int K, int N)
{
    __shared__ float t[32][33];
    int n0 = blockIdx.x * 32, k0 = blockIdx.y * 32;
    src += (size_t)blockIdx.z * K * N;
    dst += (size_t)blockIdx.z * K * N;
    int tx = threadIdx.x & 31, ty = threadIdx.x >> 5;
#pragma unroll
    for (int i = ty; i < 32; i += 8)
        t[i][tx] = src[(size_t)(k0 + i) * N + n0 + tx];
    __syncthreads();
#pragma unroll
    for (int i = ty; i < 32; i += 8)
        dst[(size_t)(n0 + i) * K + k0 + tx] = __float2half_rn(t[tx][i]);
}

// ---------------- V transpose: qkv fp16 -> Vt[bh][d][j] ---------------------
__global__ void __launch_bounds__(256) vtrans_kernel(
    const __half* __restrict__ qkv, __half* __restrict__ vt)
{
    __shared__ __half t[64][66];
    int bh = blockIdx.y;
    int b = bh >> 4, h = bh & 15;
    int j0 = blockIdx.x * 64;
    const __half* src = qkv + (size_t)b * N_ * 3 * D_ + 2 * D_ + (size_t)h * DH_;
    __half* dst = vt + (size_t)bh * DH_ * N_;
    int tid = threadIdx.x;
#pragma unroll
    for (int i = 0; i < 16; i++) {
        int idx = tid + i * 256;
        int j = idx >> 6, d = idx & 63;
        t[j][d] = src[(size_t)(j0 + j) * 3 * D_ + d];
    }
    __syncthreads();
#pragma unroll
    for (int i = 0; i < 16; i++) {
        int idx = tid + i * 256;
        int d = idx >> 6, j = idx & 63;
        dst[(size_t)d * N_ + j0 + j] = t[j][d];
    }
}

// ---------------- LayerNorm (emits fp16) -----------------------------------
__global__ void __launch_bounds__(256) ln_kernel(
    const float* __restrict__ x, const float* __restrict__ s,
    const float* __restrict__ b, __half* __restrict__ o)
{
    __shared__ float red[2][8];
    int row = blockIdx.x;
    const float* xr = x + (size_t)row * D_;
    __half* orow = o + (size_t)row * D_;
    int t = threadIdx.x;
    float v[4];
    float sum = 0.f, sq = 0.f;
#pragma unroll
    for (int i = 0; i < 4; i++) {
        float z = xr[t + i * 256];
        v[i] = z; sum += z; sq += z * z;
    }
#pragma unroll
    for (int off = 16; off > 0; off >>= 1) {
        sum += __shfl_xor_sync(0xffffffffu, sum, off);
        sq  += __shfl_xor_sync(0xffffffffu, sq,  off);
    }
    if ((t & 31) == 0) { red[0][t >> 5] = sum; red[1][t >> 5] = sq; }
    __syncthreads();
    sum = 0.f; sq = 0.f;
#pragma unroll
    for (int i = 0; i < 8; i++) { sum += red[0][i]; sq += red[1][i]; }
    float mean = sum * (1.f / D_);
    float var  = sq  * (1.f / D_) - mean * mean;
    float rstd = rsqrtf(var + 1e-5f);
#pragma unroll
    for (int i = 0; i < 4; i++) {
        int c = t + i * 256;
        orow[c] = __float2half_rn((v[i] - mean) * rstd * s[c] + b[c]);
    }
}

// ---------------- fp16 tensor-core GEMM, cp.async, 2 CTAs/SM ----------------
// A: [M][K] fp16. Wt: [N][K] fp16. BM=128, BN=128, BK=64, 256 thr (8 warps,
// 4m x 2n, warp tile 32x64). EPI bit0:+bias bit1:gelu bit2:+res. OH: fp16 out.
// SPLITK: grid.z selects K-half; writes fp32 partials (no epilogue).
template<int EPI, int OH, int SPLITK>
__global__ void __launch_bounds__(256, 2) gemm_hf(
    const __half* __restrict__ A, const __half* __restrict__ Wt,
    const float* __restrict__ bias, const float* __restrict__ res,
    void* __restrict__ Cv, int M, int N, int K)
{
    const int MI = 2, NI = 8;            // WM=32, WN=64
    const int RS = 144;
    const int A_BYTES = 128 * RS;
    const int B_BYTES = 128 * RS;

    extern __shared__ char sm[];
    char* Asm = sm;
    char* Bsm = sm + 2 * A_BYTES;

    int tid = threadIdx.x;
    int bx = blockIdx.x, by = blockIdx.y;
    int wid = tid >> 5, lane = tid & 31;
    int wn = wid & 1, wm = wid >> 1;
    int g = lane >> 2, q = lane & 3;

    const __half* Ab = A  + (size_t)by * 128 * K;
    const __half* Bb = Wt + (size_t)bx * 128 * K;
    int KT = K / 64;
    int kt_lo = 0, kt_hi = KT;
    if (SPLITK) {
        int half = KT >> 1;
        kt_lo = blockIdx.z * half;
        kt_hi = kt_lo + half;
    }

    float acc[MI][NI][4];
#pragma unroll
    for (int mi = 0; mi < MI; mi++)
#pragma unroll
        for (int ni = 0; ni < NI; ni++)
#pragma unroll
            for (int k = 0; k < 4; k++) acc[mi][ni][k] = 0.f;

    auto load_tile = [&](int kt, int s) {
#pragma unroll
        for (int i = 0; i < 4; i++) {
            int idx = tid + i * 256;
            int r = idx >> 3, c = idx & 7;
            cp16(Asm + s * A_BYTES + r * RS + c * 16,
                 Ab + (size_t)r * K + kt * 64 + c * 8);
        }
#pragma unroll
        for (int i = 0; i < 4; i++) {
            int idx = tid + i * 256;
            int r = idx >> 3, c = idx & 7;
            cp16(Bsm + s * B_BYTES + r * RS + c * 16,
                 Bb + (size_t)r * K + kt * 64 + c * 8);
        }
        cp_commit();
    };

    load_tile(kt_lo, 0);

    for (int kt = kt_lo; kt < kt_hi; kt++) {
        int s = (kt - kt_lo) & 1;
        if (kt + 1 < kt_hi) {
            load_tile(kt + 1, (kt + 1 - kt_lo) & 1);
            asm volatile("cp.async.wait_group 1;");
        } else {
            asm volatile("cp.async.wait_group 0;");
        }
        __syncthreads();
        const char* As = Asm + s * A_BYTES;
        const char* Bs = Bsm + s * B_BYTES;
#pragma unroll
        for (int ks = 0; ks < 4; ks++) {
            int kb = ks * 32;
            uint32_t a[MI][4];
#pragma unroll
            for (int mi = 0; mi < MI; mi++) {
                const char* p0 = As + (wm * 32 + mi * 16 + g) * RS + kb + 4 * q;
                const char* p1 = As + (wm * 32 + mi * 16 + 8 + g) * RS + kb + 4 * q;
                a[mi][0] = *(const uint32_t*)(p0);
                a[mi][1] = *(const uint32_t*)(p1);
                a[mi][2] = *(const uint32_t*)(p0 + 16);
                a[mi][3] = *(const uint32_t*)(p1 + 16);
            }
            uint32_t b[NI][2];
#pragma unroll
            for (int ni = 0; ni < NI; ni++) {
                const char* pb = Bs + (wn * 64 + ni * 8 + g) * RS + kb + 4 * q;
                b[ni][0] = *(const uint32_t*)(pb);
                b[ni][1] = *(const uint32_t*)(pb + 16);
            }
#pragma unroll
            for (int mi = 0; mi < MI; mi++)
#pragma unroll
                for (int ni = 0; ni < NI; ni++) mma16(acc[mi][ni], a[mi], b[ni]);
        }
        __syncthreads();
    }

    size_t zoff = SPLITK ? (size_t)blockIdx.z * M * N : 0;
#pragma unroll
    for (int mi = 0; mi < MI; mi++) {
        int r0 = by * 128 + wm * 32 + mi * 16 + g;
#pragma unroll
        for (int ni = 0; ni < NI; ni++) {
            int c = bx * 128 + wn * 64 + ni * 8 + q * 2;
            float2 v0 = make_float2(acc[mi][ni][0], acc[mi][ni][1]);
            float2 v1 = make_float2(acc[mi][ni][2], acc[mi][ni][3]);
            if (EPI & 1) {
                float b0 = bias[c], b1 = bias[c + 1];
                v0.x += b0; v0.y += b1; v1.x += b0; v1.y += b1;
            }
            if (EPI & 2) {
                const float is2 = 0.70710678118654752f;
                v0.x = 0.5f * v0.x * (1.f + erff(v0.x * is2));
                v0.y = 0.5f * v0.y * (1.f + erff(v0.y * is2));
                v1.x = 0.5f * v1.x * (1.f + erff(v1.x * is2));
                v1.y = 0.5f * v1.y * (1.f + erff(v1.y * is2));
            }
            size_t a0 = zoff + (size_t)r0 * N + c;
            size_t a1 = zoff + (size_t)(r0 + 8) * N + c;
            if (EPI & 4) {
                float2 r0v = *(const float2*)(res + a0);
                float2 r1v = *(const float2*)(res + a1);
                v0.x += r0v.x; v0.y += r0v.y; v1.x += r1v.x; v1.y += r1v.y;
            }
            if (OH) {
                __half* C = (__half*)Cv;
                *(__half2*)(C + a0) = __floats2half2_rn(v0.x, v0.y);
                *(__half2*)(C + a1) = __floats2half2_rn(v1.x, v1.y);
            } else {
                float* C = (float*)Cv;
                *(float2*)(C + a0) = v0;
                *(float2*)(C + a1) = v1;
            }
        }
    }
}

// ---------------- split-K combine: out += part0 + part1 + bias --------------
__global__ void __launch_bounds__(256) combine_sk(
    const float* __restrict__ part, const float* __restrict__ bias,
    float* __restrict__ out)
{
    int idx = blockIdx.x * 256 + threadIdx.x;      // over M*D/4 float4
    const float4* p0 = (const float4*)part;
    const float4* p1 = (const float4*)(part + (size_t)M_ * D_);
    float4 a = p0[idx], b = p1[idx];
    float4 o = ((float4*)out)[idx];
    const float4 bb = *(const float4*)(bias + (idx * 4) % D_);
    o.x += a.x + b.x + bb.x;
    o.y += a.y + b.y + bb.y;
    o.z += a.z + b.z + bb.z;
    o.w += a.w + b.w + bb.w;
    ((float4*)out)[idx] = o;
}

// ---------------- fused flash attention (fp16) ------------------------------
#define FL_RS    144
#define FL_Q     0
#define FL_K     (128 * FL_RS)
#define FL_V     (FL_K + 2 * 64 * FL_RS)
#define FL_P     (FL_V + 2 * 64 * FL_RS)
#define FL_SMEM  (FL_P + 8 * 16 * FL_RS)    /* 73728 */

__global__ void __launch_bounds__(256, 2) flash_hf(
    const __half* __restrict__ qkv, const __half* __restrict__ vt,
    __half* __restrict__ o)
{
    const int RS = FL_RS;
    extern __shared__ char sm[];
    char* Qs = sm + FL_Q;
    char* Ks = sm + FL_K;
    char* Vs = sm + FL_V;

    int bh = blockIdx.y;
    int b = bh >> 4, h = bh & 15;
    int i0 = blockIdx.x * 128;
    const __half* Qb  = qkv + (size_t)b * N_ * 3 * D_ + (size_t)h * DH_;
    const __half* Kb  = Qb + D_;
    const __half* Vtb = vt + (size_t)bh * DH_ * N_;

    int tid = threadIdx.x, wid = tid >> 5, lane = tid & 31;
    int g = lane >> 2, q = lane & 3;
    char* Pw = sm + FL_P + wid * 16 * RS;

#pragma unroll
    for (int i = 0; i < 4; i++) {
        int idx = tid + i * 256;
        int r = idx >> 3, c = idx & 7;
        cp16(Qs + r * RS + c * 16, Qb + (size_t)(i0 + r) * 3 * D_ + c * 8);
    }
    cp_commit();

    auto load_kv = [&](int kt, int s) {
        int j0 = kt * 64;
#pragma unroll
        for (int i = 0; i < 2; i++) {
            int idx = tid + i * 256;
            int r = idx >> 3, c = idx & 7;
            cp16(Ks + s * 64 * RS + r * RS + c * 16,
                 Kb + (size_t)(j0 + r) * 3 * D_ + c * 8);
            cp16(Vs + s * 64 * RS + r * RS + c * 16,
                 Vtb + (size_t)r * N_ + j0 + c * 8);
        }
        cp_commit();
    };

    load_kv(0, 0);

    float oacc[8][4];
#pragma unroll
    for (int ni = 0; ni < 8; ni++)
#pragma unroll
        for (int k = 0; k < 4; k++) oacc[ni][k] = 0.f;
    float mr0 = -1e30f, mr1 = -1e30f, lr0 = 0.f, lr1 = 0.f;

    const float scale = 0.03125f;
    char* Qw = Qs + wid * 16 * RS;

    for (int kt = 0; kt < 16; kt++) {
        int s = kt & 1;
        if (kt + 1 < 16) {
            load_kv(kt + 1, (kt + 1) & 1);
            asm volatile("cp.async.wait_group 1;");
        } else {
            asm volatile("cp.async.wait_group 0;");
        }
        __syncthreads();
        const char* Kc = Ks + s * 64 * RS;
        const char* Vc = Vs + s * 64 * RS;

        float sacc[8][4];
#pragma unroll
        for (int ni = 0; ni < 8; ni++)
#pragma unroll
            for (int k = 0; k < 4; k++) sacc[ni][k] = 0.f;
#pragma unroll
        for (int ks = 0; ks < 4; ks++) {
            int kb = ks * 32;
            uint32_t a[4];
            const char* p0 = Qw + g * RS + kb + 4 * q;
            const char* p1 = Qw + (8 + g) * RS + kb + 4 * q;
            a[0] = *(const uint32_t*)(p0);
            a[1] = *(const uint32_t*)(p1);
            a[2] = *(const uint32_t*)(p0 + 16);
            a[3] = *(const uint32_t*)(p1 + 16);
#pragma unroll
            for (int ni = 0; ni < 8; ni++) {
                uint32_t b2[2];
                const char* pb = Kc + (ni * 8 + g) * RS + kb + 4 * q;
                b2[0] = *(const uint32_t*)(pb);
                b2[1] = *(const uint32_t*)(pb + 16);
                mma16(sacc[ni], a, b2);
            }
        }

        float mx0 = -1e30f, mx1 = -1e30f;
#pragma unroll
        for (int ni = 0; ni < 8; ni++) {
            sacc[ni][0] *= scale; sacc[ni][1] *= scale;
            sacc[ni][2] *= scale; sacc[ni][3] *= scale;
            mx0 = fmaxf(mx0, fmaxf(sacc[ni][0], sacc[ni][1]));
            mx1 = fmaxf(mx1, fmaxf(sacc[ni][2], sacc[ni][3]));
        }
        mx0 = fmaxf(mx0, __shfl_xor_sync(0xffffffffu, mx0, 1));
        mx0 = fmaxf(mx0, __shfl_xor_sync(0xffffffffu, mx0, 2));
        mx1 = fmaxf(mx1, __shfl_xor_sync(0xffffffffu, mx1, 1));
        mx1 = fmaxf(mx1, __shfl_xor_sync(0xffffffffu, mx1, 2));
        float mn0 = fmaxf(mr0, mx0), mn1 = fmaxf(mr1, mx1);
        float corr0 = __expf(mr0 - mn0), corr1 = __expf(mr1 - mn1);
        mr0 = mn0; mr1 = mn1;

        float ls0 = 0.f, ls1 = 0.f;
#pragma unroll
        for (int ni = 0; ni < 8; ni++) {
            float p0 = __expf(sacc[ni][0] - mn0);
            float p1 = __expf(sacc[ni][1] - mn0);
            float p2 = __expf(sacc[ni][2] - mn1);
            float p3 = __expf(sacc[ni][3] - mn1);
            ls0 += p0 + p1; ls1 += p2 + p3;
            int cb = ni * 16 + 4 * q;
            *(__half2*)(Pw + g * RS + cb)       = __floats2half2_rn(p0, p1);
            *(__half2*)(Pw + (8 + g) * RS + cb) = __floats2half2_rn(p2, p3);
        }
        lr0 = lr0 * corr0 + ls0;
        lr1 = lr1 * corr1 + ls1;
#pragma unroll
        for (int ni = 0; ni < 8; ni++) {
            oacc[ni][0] *= corr0; oacc[ni][1] *= corr0;
            oacc[ni][2] *= corr1; oacc[ni][3] *= corr1;
        }
        __syncwarp();

#pragma unroll
        for (int ks = 0; ks < 4; ks++) {
            int kb = ks * 32;
            uint32_t a[4];
            const char* p0 = Pw + g * RS + kb + 4 * q;
            const char* p1 = Pw + (8 + g) * RS + kb + 4 * q;
            a[0] = *(const uint32_t*)(p0);
            a[1] = *(const uint32_t*)(p1);
            a[2] = *(const uint32_t*)(p0 + 16);
            a[3] = *(const uint32_t*)(p1 + 16);
#pragma unroll
            for (int ni = 0; ni < 8; ni++) {
                uint32_t b2[2];
                const char* pb = Vc + (ni * 8 + g) * RS + kb + 4 * q;
                b2[0] = *(const uint32_t*)(pb);
                b2[1] = *(const uint32_t*)(pb + 16);
                mma16(oacc[ni], a, b2);
            }
        }
        __syncthreads();
    }

    lr0 += __shfl_xor_sync(0xffffffffu, lr0, 1);
    lr0 += __shfl_xor_sync(0xffffffffu, lr0, 2);
    lr1 += __shfl_xor_sync(0xffffffffu, lr1, 1);
    lr1 += __shfl_xor_sync(0xffffffffu, lr1, 2);
    float inv0 = 1.f / lr0, inv1 = 1.f / lr1;

    int r0 = i0 + wid * 16 + g, r1 = r0 + 8;
#pragma unroll
    for (int ni = 0; ni < 8; ni++) {
        int c = h * DH_ + ni * 8 + q * 2;
        size_t a0 = ((size_t)b * N_ + r0) * D_ + c;
        size_t a1 = ((size_t)b * N_ + r1) * D_ + c;
        *(__half2*)(o + a0) = __floats2half2_rn(oacc[ni][0] * inv0, oacc[ni][1] * inv0);
        *(__half2*)(o + a1) = __floats2half2_rn(oacc[ni][2] * inv1, oacc[ni][3] * inv1);
    }
}

// ---------------- orchestration --------------------------------------------
#define HF_SMEM (2 * (128 * 144) + 2 * (128 * 144))   /* 73728 -> 2 CTAs/SM */

extern "C" void kernel_launch(void* const* d_in, const int* in_sizes, int n_in,
                              void* d_out, int out_size)
{
    (void)in_sizes; (void)n_in; (void)out_size;
    const float* x     = (const float*)d_in[0];
    const float* ln1_s = (const float*)d_in[1];
    const float* ln1_b = (const float*)d_in[2];
    const float* w_qkv = (const float*)d_in[3];
    const float* w_out = (const float*)d_in[4];
    const float* b_out = (const float*)d_in[5];
    const float* ln2_s = (const float*)d_in[6];
    const float* ln2_b = (const float*)d_in[7];
    const float* w1    = (const float*)d_in[8];
    const float* b1    = (const float*)d_in[9];
    const float* w2    = (const float*)d_in[10];
    const float* b2    = (const float*)d_in[11];
    float* out = (float*)d_out;

    __half *h, *qkv, *vt, *o, *mlp, *wqkv, *wout, *w1t, *w2t;
    float *part;
    cudaGetSymbolAddress((void**)&h,    g_h);
    cudaGetSymbolAddress((void**)&qkv,  g_qkv);
    cudaGetSymbolAddress((void**)&vt,   g_vt);
    cudaGetSymbolAddress((void**)&o,    g_o);
    cudaGetSymbolAddress((void**)&mlp,  g_mlp);
    cudaGetSymbolAddress((void**)&part, g_part);
    cudaGetSymbolAddress((void**)&wqkv, g_wqkv);
    cudaGetSymbolAddress((void**)&wout, g_wout);
    cudaGetSymbolAddress((void**)&w1t,  g_w1);
    cudaGetSymbolAddress((void**)&w2t,  g_w2);

    cudaFuncSetAttribute(gemm_hf<0, 1, 0>,
        cudaFuncAttributeMaxDynamicSharedMemorySize, HF_SMEM);
    cudaFuncSetAttribute(gemm_hf<3, 1, 0>,
        cudaFuncAttributeMaxDynamicSharedMemorySize, HF_SMEM);
    cudaFuncSetAttribute(gemm_hf<0, 0, 1>,
        cudaFuncAttributeMaxDynamicSharedMemorySize, HF_SMEM);
    cudaFuncSetAttribute(flash_hf,
        cudaFuncAttributeMaxDynamicSharedMemorySize, FL_SMEM);

    // pre-pass: weights -> [N][K] fp16
    wtrans_kernel<<<dim3(3 * D_ / 32, D_ / 32, DEPTH_), 256>>>(w_qkv, wqkv, D_, 3 * D_);
    wtrans_kernel<<<dim3(D_ / 32, D_ / 32, DEPTH_), 256>>>(w_out, wout, D_, D_);
    wtrans_kernel<<<dim3(MLP_ / 32, D_ / 32, DEPTH_), 256>>>(w1, w1t, D_, MLP_);
    wtrans_kernel<<<dim3(D_ / 32, MLP_ / 32, DEPTH_), 256>>>(w2, w2t, MLP_, D_);

    cudaMemcpyAsync(out, x, (size_t)M_ * D_ * sizeof(float),
                    cudaMemcpyDeviceToDevice);

    const int CB = M_ * D_ / 4 / 256;   // combine grid: 2048 blocks

    for (int l = 0; l < DEPTH_; l++) {
        // --- attention block ---
        ln_kernel<<<M_, 256>>>(out, ln1_s + (size_t)l * D_, ln1_b + (size_t)l * D_, h);
        gemm_hf<0, 1, 0><<<dim3(3 * D_ / 128, M_ / 128), 256, HF_SMEM>>>(
            h, wqkv + (size_t)l * D_ * 3 * D_, nullptr, nullptr,
            qkv, M_, 3 * D_, D_);
        vtrans_kernel<<<dim3(N_ / 64, B_ * H_), 256>>>(qkv, vt);
        flash_hf<<<dim3(N_ / 128, B_ * H_), 256, FL_SMEM>>>(qkv, vt, o);
        // out-proj: split-K=2 partials + combine (adds bias + residual)
        gemm_hf<0, 0, 1><<<dim3(D_ / 128, M_ / 128, 2), 256, HF_SMEM>>>(
            o, wout + (size_t)l * D_ * D_, nullptr, nullptr,
            part, M_, D_, D_);
        combine_sk<<<CB, 256>>>(part, b_out + (size_t)l * D_, out);
        // --- MLP block ---
        ln_kernel<<<M_, 256>>>(out, ln2_s + (size_t)l * D_, ln2_b + (size_t)l * D_, h);
        gemm_hf<3, 1, 0><<<dim3(MLP_ / 128, M_ / 128), 256, HF_SMEM>>>(
            h, w1t + (size_t)l * D_ * MLP_, b1 + (size_t)l * MLP_,
            nullptr, mlp, M_, MLP_, D_);
        // MLP2: split-K=2 partials + combine
        gemm_hf<0, 0, 1><<<dim3(D_ / 128, M_ / 128, 2), 256, HF_SMEM>>>(
            mlp, w2t + (size_t)l * MLP_ * D_, nullptr, nullptr,
            part, M_, D_, MLP_);
        combine_sk<<<CB, 256>>>(part, b2 + (size_t)l * D_, out);
    }
}

// round 15
// speedup vs baseline: 1.0800x; 1.0088x over previous
#include <cuda_runtime.h>
#include <cuda_fp16.h>
#include <math.h>
#include <stdint.h>

#define B_    2
#define N_    1024
#define D_    1024
#define H_    16
#define DH_   64
#define MLP_  4096
#define DEPTH_ 6
#define M_    (B_ * N_)   /* 2048 rows */

// ---------------- scratch -----------------------------------------------
__device__ __half g_h  [(size_t)M_ * D_];
__device__ __half g_qkv[(size_t)M_ * 3 * D_];
__device__ __half g_vt [(size_t)B_ * H_ * DH_ * N_];
__device__ __half g_o  [(size_t)M_ * D_];
__device__ __half g_mlp[(size_t)M_ * MLP_];
__device__ __half g_wqkv[(size_t)DEPTH_ * D_ * 3 * D_];
__device__ __half g_wout[(size_t)DEPTH_ * D_ * D_];
__device__ __half g_w1  [(size_t)DEPTH_ * D_ * MLP_];
__device__ __half g_w2  [(size_t)DEPTH_ * MLP_ * D_];

// ---------------- helpers ---------------------------------------------------
__device__ __forceinline__ void mma16(float* d, const uint32_t* a, const uint32_t* b) {
    asm volatile(
        "mma.sync.aligned.m16n8k16.row.col.f32.f16.f16.f32 "
        "{%0,%1,%2,%3},{%4,%5,%6,%7},{%8,%9},{%0,%1,%2,%3};"
        : "+f"(d[0]), "+f"(d[1]), "+f"(d[2]), "+f"(d[3])
        : "r"(a[0]), "r"(a[1]), "r"(a[2]), "r"(a[3]),
          "r"(b[0]), "r"(b[1]));
}
__device__ __forceinline__ void cp16(void* smem_dst, const void* gmem_src) {
    uint32_t dst = (uint32_t)__cvta_generic_to_shared(smem_dst);
    asm volatile("cp.async.cg.shared.global [%0], [%1], 16;"
                 :: "r"(dst), "l"(gmem_src));
}
__device__ __forceinline__ void cp_commit() {
    asm volatile("cp.async.commit_group;");
}

// ---------------- weight pre-pass: [K,N] fp32 -> [N,K] fp16 -----------------
__global__ void __launch_bounds__(256) wtrans_kernel(
    const float* __restrict__ src, __half* __restrict__ dst, int K, int N)
{
    __shared__ float t[32][33];
    int n0 = blockIdx.x * 32, k0 = blockIdx.y * 32;
    src += (size_t)blockIdx.z * K * N;
    dst += (size_t)blockIdx.z * K * N;
    int tx = threadIdx.x & 31, ty = threadIdx.x >> 5;
#pragma unroll
    for (int i = ty; i < 32; i += 8)
        t[i][tx] = src[(size_t)(k0 + i) * N + n0 + tx];
    __syncthreads();
#pragma unroll
    for (int i = ty; i < 32; i += 8)
        dst[(size_t)(n0 + i) * K + k0 + tx] = __float2half_rn(t[tx][i]);
}

// ---------------- V transpose: qkv fp16 -> Vt[bh][d][j] ---------------------
__global__ void __launch_bounds__(256) vtrans_kernel(
    const __half* __restrict__ qkv, __half* __restrict__ vt)
{
    __shared__ __half t[64][66];
    int bh = blockIdx.y;
    int b = bh >> 4, h = bh & 15;
    int j0 = blockIdx.x * 64;
    const __half* src = qkv + (size_t)b * N_ * 3 * D_ + 2 * D_ + (size_t)h * DH_;
    __half* dst = vt + (size_t)bh * DH_ * N_;
    int tid = threadIdx.x;
#pragma unroll
    for (int i = 0; i < 16; i++) {
        int idx = tid + i * 256;
        int j = idx >> 6, d = idx & 63;
        t[j][d] = src[(size_t)(j0 + j) * 3 * D_ + d];
    }
    __syncthreads();
#pragma unroll
    for (int i = 0; i < 16; i++) {
        int idx = tid + i * 256;
        int d = idx >> 6, j = idx & 63;
        dst[(size_t)d * N_ + j0 + j] = t[j][d];
    }
}

// ---------------- LayerNorm (emits fp16) -----------------------------------
__global__ void __launch_bounds__(256) ln_kernel(
    const float* __restrict__ x, const float* __restrict__ s,
    const float* __restrict__ b, __half* __restrict__ o)
{
    __shared__ float red[2][8];
    int row = blockIdx.x;
    const float* xr = x + (size_t)row * D_;
    __half* orow = o + (size_t)row * D_;
    int t = threadIdx.x;
    float v[4];
    float sum = 0.f, sq = 0.f;
#pragma unroll
    for (int i = 0; i < 4; i++) {
        float z = xr[t + i * 256];
        v[i] = z; sum += z; sq += z * z;
    }
#pragma unroll
    for (int off = 16; off > 0; off >>= 1) {
        sum += __shfl_xor_sync(0xffffffffu, sum, off);
        sq  += __shfl_xor_sync(0xffffffffu, sq,  off);
    }
    if ((t & 31) == 0) { red[0][t >> 5] = sum; red[1][t >> 5] = sq; }
    __syncthreads();
    sum = 0.f; sq = 0.f;
#pragma unroll
    for (int i = 0; i < 8; i++) { sum += red[0][i]; sq += red[1][i]; }
    float mean = sum * (1.f / D_);
    float var  = sq  * (1.f / D_) - mean * mean;
    float rstd = rsqrtf(var + 1e-5f);
#pragma unroll
    for (int i = 0; i < 4; i++) {
        int c = t + i * 256;
        orow[c] = __float2half_rn((v[i] - mean) * rstd * s[c] + b[c]);
    }
}

// ---------------- fp16 tensor-core GEMM, 3-stage cp.async, 2 CTAs/SM --------
// A: [M][K] fp16. Wt: [N][K] fp16. BM=128, BN=128, BK=64, 256 thr (8 warps,
// 4m x 2n, warp tile 32x64). One __syncthreads per k-iter.
// EPI bit0:+bias bit1:gelu bit2:+res.  OH: write __half output.
template<int EPI, int OH>
__global__ void __launch_bounds__(256, 2) gemm_hf(
    const __half* __restrict__ A, const __half* __restrict__ Wt,
    const float* __restrict__ bias, const float* __restrict__ res,
    void* __restrict__ Cv, int M, int N, int K)
{
    const int MI = 2, NI = 8;            // WM=32, WN=64
    const int RS = 144;
    const int A_BYTES = 128 * RS;
    const int B_BYTES = 128 * RS;

    extern __shared__ char sm[];
    char* Asm = sm;
    char* Bsm = sm + 3 * A_BYTES;

    int tid = threadIdx.x;
    int bx = blockIdx.x, by = blockIdx.y;
    int wid = tid >> 5, lane = tid & 31;
    int wn = wid & 1, wm = wid >> 1;
    int g = lane >> 2, q = lane & 3;

    const __half* Ab = A  + (size_t)by * 128 * K;
    const __half* Bb = Wt + (size_t)bx * 128 * K;
    int KT = K / 64;

    float acc[MI][NI][4];
#pragma unroll
    for (int mi = 0; mi < MI; mi++)
#pragma unroll
        for (int ni = 0; ni < NI; ni++)
#pragma unroll
            for (int k = 0; k < 4; k++) acc[mi][ni][k] = 0.f;

    auto load_tile = [&](int kt, int s) {
#pragma unroll
        for (int i = 0; i < 4; i++) {
            int idx = tid + i * 256;
            int r = idx >> 3, c = idx & 7;
            cp16(Asm + s * A_BYTES + r * RS + c * 16,
                 Ab + (size_t)r * K + kt * 64 + c * 8);
        }
#pragma unroll
        for (int i = 0; i < 4; i++) {
            int idx = tid + i * 256;
            int r = idx >> 3, c = idx & 7;
            cp16(Bsm + s * B_BYTES + r * RS + c * 16,
                 Bb + (size_t)r * K + kt * 64 + c * 8);
        }
        cp_commit();
    };

    load_tile(0, 0);
    load_tile(1, 1);

    for (int kt = 0; kt < KT; kt++) {
        if (kt + 1 < KT) {
            asm volatile("cp.async.wait_group 1;");
        } else {
            asm volatile("cp.async.wait_group 0;");
        }
        __syncthreads();   // tile kt visible; all warps done with buf (kt+2)%3
        if (kt + 2 < KT) load_tile(kt + 2, (kt + 2) % 3);
        int s = kt % 3;
        const char* As = Asm + s * A_BYTES;
        const char* Bs = Bsm + s * B_BYTES;
#pragma unroll
        for (int ks = 0; ks < 4; ks++) {
            int kb = ks * 32;
            uint32_t a[MI][4];
#pragma unroll
            for (int mi = 0; mi < MI; mi++) {
                const char* p0 = As + (wm * 32 + mi * 16 + g) * RS + kb + 4 * q;
                const char* p1 = As + (wm * 32 + mi * 16 + 8 + g) * RS + kb + 4 * q;
                a[mi][0] = *(const uint32_t*)(p0);
                a[mi][1] = *(const uint32_t*)(p1);
                a[mi][2] = *(const uint32_t*)(p0 + 16);
                a[mi][3] = *(const uint32_t*)(p1 + 16);
            }
            uint32_t b[NI][2];
#pragma unroll
            for (int ni = 0; ni < NI; ni++) {
                const char* pb = Bs + (wn * 64 + ni * 8 + g) * RS + kb + 4 * q;
                b[ni][0] = *(const uint32_t*)(pb);
                b[ni][1] = *(const uint32_t*)(pb + 16);
            }
#pragma unroll
            for (int mi = 0; mi < MI; mi++)
#pragma unroll
                for (int ni = 0; ni < NI; ni++) mma16(acc[mi][ni], a[mi], b[ni]);
        }
    }

#pragma unroll
    for (int mi = 0; mi < MI; mi++) {
        int r0 = by * 128 + wm * 32 + mi * 16 + g;
#pragma unroll
        for (int ni = 0; ni < NI; ni++) {
            int c = bx * 128 + wn * 64 + ni * 8 + q * 2;
            float2 v0 = make_float2(acc[mi][ni][0], acc[mi][ni][1]);
            float2 v1 = make_float2(acc[mi][ni][2], acc[mi][ni][3]);
            if (EPI & 1) {
                float b0 = bias[c], b1 = bias[c + 1];
                v0.x += b0; v0.y += b1; v1.x += b0; v1.y += b1;
            }
            if (EPI & 2) {
                const float is2 = 0.70710678118654752f;
                v0.x = 0.5f * v0.x * (1.f + erff(v0.x * is2));
                v0.y = 0.5f * v0.y * (1.f + erff(v0.y * is2));
                v1.x = 0.5f * v1.x * (1.f + erff(v1.x * is2));
                v1.y = 0.5f * v1.y * (1.f + erff(v1.y * is2));
            }
            size_t a0 = (size_t)r0 * N + c;
            size_t a1 = (size_t)(r0 + 8) * N + c;
            if (EPI & 4) {
                float2 r0v = *(const float2*)(res + a0);
                float2 r1v = *(const float2*)(res + a1);
                v0.x += r0v.x; v0.y += r0v.y; v1.x += r1v.x; v1.y += r1v.y;
            }
            if (OH) {
                __half* C = (__half*)Cv;
                *(__half2*)(C + a0) = __floats2half2_rn(v0.x, v0.y);
                *(__half2*)(C + a1) = __floats2half2_rn(v1.x, v1.y);
            } else {
                float* C = (float*)Cv;
                *(float2*)(C + a0) = v0;
                *(float2*)(C + a1) = v1;
            }
        }
    }
}

// ---------------- fused flash attention (fp16, 3-stage KV pipeline) ---------
// grid (N/128 = 8, B*H = 32), 256 thr = 8 warps; warp w owns q-rows w*16..+15.
// smem: Q 18K | K 3x9K | Vt 3x9K | P 8x2.25K = 92160 -> 2 CTAs/SM.
#define FL_RS    144
#define FL_Q     0
#define FL_K     (128 * FL_RS)
#define FL_V     (FL_K + 3 * 64 * FL_RS)
#define FL_P     (FL_V + 3 * 64 * FL_RS)
#define FL_SMEM  (FL_P + 8 * 16 * FL_RS)    /* 92160 */

__global__ void __launch_bounds__(256, 2) flash_hf(
    const __half* __restrict__ qkv, const __half* __restrict__ vt,
    __half* __restrict__ o)
{
    const int RS = FL_RS;
    extern __shared__ char sm[];
    char* Qs = sm + FL_Q;
    char* Ks = sm + FL_K;
    char* Vs = sm + FL_V;

    int bh = blockIdx.y;
    int b = bh >> 4, h = bh & 15;
    int i0 = blockIdx.x * 128;
    const __half* Qb  = qkv + (size_t)b * N_ * 3 * D_ + (size_t)h * DH_;
    const __half* Kb  = Qb + D_;
    const __half* Vtb = vt + (size_t)bh * DH_ * N_;

    int tid = threadIdx.x, wid = tid >> 5, lane = tid & 31;
    int g = lane >> 2, q = lane & 3;
    char* Pw = sm + FL_P + wid * 16 * RS;

#pragma unroll
    for (int i = 0; i < 4; i++) {
        int idx = tid + i * 256;
        int r = idx >> 3, c = idx & 7;
        cp16(Qs + r * RS + c * 16, Qb + (size_t)(i0 + r) * 3 * D_ + c * 8);
    }
    cp_commit();

    auto load_kv = [&](int kt, int s) {
        int j0 = kt * 64;
#pragma unroll
        for (int i = 0; i < 2; i++) {
            int idx = tid + i * 256;
            int r = idx >> 3, c = idx & 7;
            cp16(Ks + s * 64 * RS + r * RS + c * 16,
                 Kb + (size_t)(j0 + r) * 3 * D_ + c * 8);
            cp16(Vs + s * 64 * RS + r * RS + c * 16,
                 Vtb + (size_t)r * N_ + j0 + c * 8);
        }
        cp_commit();
    };

    load_kv(0, 0);
    load_kv(1, 1);

    float oacc[8][4];
#pragma unroll
    for (int ni = 0; ni < 8; ni++)
#pragma unroll
        for (int k = 0; k < 4; k++) oacc[ni][k] = 0.f;
    float mr0 = -1e30f, mr1 = -1e30f, lr0 = 0.f, lr1 = 0.f;

    const float scale = 0.03125f;   // D^-0.5 (full-dim per reference)
    char* Qw = Qs + wid * 16 * RS;

    for (int kt = 0; kt < 16; kt++) {
        if (kt + 1 < 16) {
            asm volatile("cp.async.wait_group 1;");
        } else {
            asm volatile("cp.async.wait_group 0;");
        }
        __syncthreads();   // chunk kt (and Q) visible; buf (kt+2)%3 free
        if (kt + 2 < 16) load_kv(kt + 2, (kt + 2) % 3);
        int s = kt % 3;
        const char* Kc = Ks + s * 64 * RS;
        const char* Vc = Vs + s * 64 * RS;

        // ---- S = Q K^T (warp: 16 x 64) ----
        float sacc[8][4];
#pragma unroll
        for (int ni = 0; ni < 8; ni++)
#pragma unroll
            for (int k = 0; k < 4; k++) sacc[ni][k] = 0.f;
#pragma unroll
        for (int ks = 0; ks < 4; ks++) {
            int kb = ks * 32;
            uint32_t a[4];
            const char* p0 = Qw + g * RS + kb + 4 * q;
            const char* p1 = Qw + (8 + g) * RS + kb + 4 * q;
            a[0] = *(const uint32_t*)(p0);
            a[1] = *(const uint32_t*)(p1);
            a[2] = *(const uint32_t*)(p0 + 16);
            a[3] = *(const uint32_t*)(p1 + 16);
#pragma unroll
            for (int ni = 0; ni < 8; ni++) {
                uint32_t b2[2];
                const char* pb = Kc + (ni * 8 + g) * RS + kb + 4 * q;
                b2[0] = *(const uint32_t*)(pb);
                b2[1] = *(const uint32_t*)(pb + 16);
                mma16(sacc[ni], a, b2);
            }
        }

        // ---- online softmax (rows g, 8+g) ----
        float mx0 = -1e30f, mx1 = -1e30f;
#pragma unroll
        for (int ni = 0; ni < 8; ni++) {
            sacc[ni][0] *= scale; sacc[ni][1] *= scale;
            sacc[ni][2] *= scale; sacc[ni][3] *= scale;
            mx0 = fmaxf(mx0, fmaxf(sacc[ni][0], sacc[ni][1]));
            mx1 = fmaxf(mx1, fmaxf(sacc[ni][2], sacc[ni][3]));
        }
        mx0 = fmaxf(mx0, __shfl_xor_sync(0xffffffffu, mx0, 1));
        mx0 = fmaxf(mx0, __shfl_xor_sync(0xffffffffu, mx0, 2));
        mx1 = fmaxf(mx1, __shfl_xor_sync(0xffffffffu, mx1, 1));
        mx1 = fmaxf(mx1, __shfl_xor_sync(0xffffffffu, mx1, 2));
        float mn0 = fmaxf(mr0, mx0), mn1 = fmaxf(mr1, mx1);
        float corr0 = __expf(mr0 - mn0), corr1 = __expf(mr1 - mn1);
        mr0 = mn0; mr1 = mn1;

        float ls0 = 0.f, ls1 = 0.f;
#pragma unroll
        for (int ni = 0; ni < 8; ni++) {
            float p0 = __expf(sacc[ni][0] - mn0);
            float p1 = __expf(sacc[ni][1] - mn0);
            float p2 = __expf(sacc[ni][2] - mn1);
            float p3 = __expf(sacc[ni][3] - mn1);
            ls0 += p0 + p1; ls1 += p2 + p3;
            int cb = ni * 16 + 4 * q;
            *(__half2*)(Pw + g * RS + cb)       = __floats2half2_rn(p0, p1);
            *(__half2*)(Pw + (8 + g) * RS + cb) = __floats2half2_rn(p2, p3);
        }
        lr0 = lr0 * corr0 + ls0;
        lr1 = lr1 * corr1 + ls1;
#pragma unroll
        for (int ni = 0; ni < 8; ni++) {
            oacc[ni][0] *= corr0; oacc[ni][1] *= corr0;
            oacc[ni][2] *= corr1; oacc[ni][3] *= corr1;
        }
        __syncwarp();

        // ---- O += P * Vt (warp: 16 x 64, k = 64) ----
#pragma unroll
        for (int ks = 0; ks < 4; ks++) {
            int kb = ks * 32;
            uint32_t a[4];
            const char* p0 = Pw + g * RS + kb + 4 * q;
            const char* p1 = Pw + (8 + g) * RS + kb + 4 * q;
            a[0] = *(const uint32_t*)(p0);
            a[1] = *(const uint32_t*)(p1);
            a[2] = *(const uint32_t*)(p0 + 16);
            a[3] = *(const uint32_t*)(p1 + 16);
#pragma unroll
            for (int ni = 0; ni < 8; ni++) {
                uint32_t b2[2];
                const char* pb = Vc + (ni * 8 + g) * RS + kb + 4 * q;
                b2[0] = *(const uint32_t*)(pb);
                b2[1] = *(const uint32_t*)(pb + 16);
                mma16(oacc[ni], a, b2);
            }
        }
    }

    lr0 += __shfl_xor_sync(0xffffffffu, lr0, 1);
    lr0 += __shfl_xor_sync(0xffffffffu, lr0, 2);
    lr1 += __shfl_xor_sync(0xffffffffu, lr1, 1);
    lr1 += __shfl_xor_sync(0xffffffffu, lr1, 2);
    float inv0 = 1.f / lr0, inv1 = 1.f / lr1;

    int r0 = i0 + wid * 16 + g, r1 = r0 + 8;
#pragma unroll
    for (int ni = 0; ni < 8; ni++) {
        int c = h * DH_ + ni * 8 + q * 2;
        size_t a0 = ((size_t)b * N_ + r0) * D_ + c;
        size_t a1 = ((size_t)b * N_ + r1) * D_ + c;
        *(__half2*)(o + a0) = __floats2half2_rn(oacc[ni][0] * inv0, oacc[ni][1] * inv0);
        *(__half2*)(o + a1) = __floats2half2_rn(oacc[ni][2] * inv1, oacc[ni][3] * inv1);
    }
}

// ---------------- orchestration --------------------------------------------
#define HF_SMEM (3 * (128 * 144) + 3 * (128 * 144))   /* 110592 -> 2 CTAs/SM */

extern "C" void kernel_launch(void* const* d_in, const int* in_sizes, int n_in,
                              void* d_out, int out_size)
{
    (void)in_sizes; (void)n_in; (void)out_size;
    const float* x     = (const float*)d_in[0];
    const float* ln1_s = (const float*)d_in[1];
    const float* ln1_b = (const float*)d_in[2];
    const float* w_qkv = (const float*)d_in[3];
    const float* w_out = (const float*)d_in[4];
    const float* b_out = (const float*)d_in[5];
    const float* ln2_s = (const float*)d_in[6];
    const float* ln2_b = (const float*)d_in[7];
    const float* w1    = (const float*)d_in[8];
    const float* b1    = (const float*)d_in[9];
    const float* w2    = (const float*)d_in[10];
    const float* b2    = (const float*)d_in[11];
    float* out = (float*)d_out;

    __half *h, *qkv, *vt, *o, *mlp, *wqkv, *wout, *w1t, *w2t;
    cudaGetSymbolAddress((void**)&h,    g_h);
    cudaGetSymbolAddress((void**)&qkv,  g_qkv);
    cudaGetSymbolAddress((void**)&vt,   g_vt);
    cudaGetSymbolAddress((void**)&o,    g_o);
    cudaGetSymbolAddress((void**)&mlp,  g_mlp);
    cudaGetSymbolAddress((void**)&wqkv, g_wqkv);
    cudaGetSymbolAddress((void**)&wout, g_wout);
    cudaGetSymbolAddress((void**)&w1t,  g_w1);
    cudaGetSymbolAddress((void**)&w2t,  g_w2);

    cudaFuncSetAttribute(gemm_hf<0, 1>,
        cudaFuncAttributeMaxDynamicSharedMemorySize, HF_SMEM);
    cudaFuncSetAttribute(gemm_hf<3, 1>,
        cudaFuncAttributeMaxDynamicSharedMemorySize, HF_SMEM);
    cudaFuncSetAttribute(gemm_hf<5, 0>,
        cudaFuncAttributeMaxDynamicSharedMemorySize, HF_SMEM);
    cudaFuncSetAttribute(flash_hf,
        cudaFuncAttributeMaxDynamicSharedMemorySize, FL_SMEM);

    // pre-pass: weights -> [N][K] fp16
    wtrans_kernel<<<dim3(3 * D_ / 32, D_ / 32, DEPTH_), 256>>>(w_qkv, wqkv, D_, 3 * D_);
    wtrans_kernel<<<dim3(D_ / 32, D_ / 32, DEPTH_), 256>>>(w_out, wout, D_, D_);
    wtrans_kernel<<<dim3(MLP_ / 32, D_ / 32, DEPTH_), 256>>>(w1, w1t, D_, MLP_);
    wtrans_kernel<<<dim3(D_ / 32, MLP_ / 32, DEPTH_), 256>>>(w2, w2t, MLP_, D_);

    cudaMemcpyAsync(out, x, (size_t)M_ * D_ * sizeof(float),
                    cudaMemcpyDeviceToDevice);

    for (int l = 0; l < DEPTH_; l++) {
        // --- attention block ---
        ln_kernel<<<M_, 256>>>(out, ln1_s + (size_t)l * D_, ln1_b + (size_t)l * D_, h);
        gemm_hf<0, 1><<<dim3(3 * D_ / 128, M_ / 128), 256, HF_SMEM>>>(
            h, wqkv + (size_t)l * D_ * 3 * D_, nullptr, nullptr,
            qkv, M_, 3 * D_, D_);
        vtrans_kernel<<<dim3(N_ / 64, B_ * H_), 256>>>(qkv, vt);
        flash_hf<<<dim3(N_ / 128, B_ * H_), 256, FL_SMEM>>>(qkv, vt, o);
        gemm_hf<5, 0><<<dim3(D_ / 128, M_ / 128), 256, HF_SMEM>>>(
            o, wout + (size_t)l * D_ * D_, b_out + (size_t)l * D_,
            out, out, M_, D_, D_);
        // --- MLP block ---
        ln_kernel<<<M_, 256>>>(out, ln2_s + (size_t)l * D_, ln2_b + (size_t)l * D_, h);
        gemm_hf<3, 1><<<dim3(MLP_ / 128, M_ / 128), 256, HF_SMEM>>>(
            h, w1t + (size_t)l * D_ * MLP_, b1 + (size_t)l * MLP_,
            nullptr, mlp, M_, MLP_, D_);
        gemm_hf<5, 0><<<dim3(D_ / 128, M_ / 128), 256, HF_SMEM>>>(
            mlp, w2t + (size_t)l * MLP_ * D_, b2 + (size_t)l * D_,
            out, out, M_, D_, MLP_);
    }
}

// round 16
// speedup vs baseline: 1.1110x; 1.0287x over previous
#include <cuda_runtime.h>
#include <cuda_fp16.h>
#include <math.h>
#include <stdint.h>

#define B_    2
#define N_    1024
#define D_    1024
#define H_    16
#define DH_   64
#define MLP_  4096
#define DEPTH_ 6
#define M_    (B_ * N_)   /* 2048 rows */

// ---------------- scratch -----------------------------------------------
__device__ __half g_h  [(size_t)M_ * D_];
__device__ __half g_qkv[(size_t)M_ * 3 * D_];
__device__ __half g_vt [(size_t)B_ * H_ * DH_ * N_];
__device__ __half g_o  [(size_t)M_ * D_];
__device__ __half g_mlp[(size_t)M_ * MLP_];
__device__ __half g_wqkv[(size_t)DEPTH_ * D_ * 3 * D_];
__device__ __half g_wout[(size_t)DEPTH_ * D_ * D_];
__device__ __half g_w1  [(size_t)DEPTH_ * D_ * MLP_];
__device__ __half g_w2  [(size_t)DEPTH_ * MLP_ * D_];

// ---------------- helpers ---------------------------------------------------
__device__ __forceinline__ void mma16(float* d, const uint32_t* a, const uint32_t* b) {
    asm volatile(
        "mma.sync.aligned.m16n8k16.row.col.f32.f16.f16.f32 "
        "{%0,%1,%2,%3},{%4,%5,%6,%7},{%8,%9},{%0,%1,%2,%3};"
        : "+f"(d[0]), "+f"(d[1]), "+f"(d[2]), "+f"(d[3])
        : "r"(a[0]), "r"(a[1]), "r"(a[2]), "r"(a[3]),
          "r"(b[0]), "r"(b[1]));
}
__device__ __forceinline__ uint32_t pack2(float x, float y) {
    __half2 h = __floats2half2_rn(x, y);
    return *(uint32_t*)&h;
}
__device__ __forceinline__ void cp16(void* smem_dst, const void* gmem_src) {
    uint32_t dst = (uint32_t)__cvta_generic_to_shared(smem_dst);
    asm volatile("cp.async.cg.shared.global [%0], [%1], 16;"
                 :: "r"(dst), "l"(gmem_src));
}
__device__ __forceinline__ void cp_commit() {
    asm volatile("cp.async.commit_group;");
}

// ---------------- weight pre-pass: [K,N] fp32 -> [N,K] fp16 -----------------
__global__ void __launch_bounds__(256) wtrans_kernel(
    const float* __restrict__ src, __half* __restrict__ dst, int K, int N)
{
    __shared__ float t[32][33];
    int n0 = blockIdx.x * 32, k0 = blockIdx.y * 32;
    src += (size_t)blockIdx.z * K * N;
    dst += (size_t)blockIdx.z * K * N;
    int tx = threadIdx.x & 31, ty = threadIdx.x >> 5;
#pragma unroll
    for (int i = ty; i < 32; i += 8)
        t[i][tx] = src[(size_t)(k0 + i) * N + n0 + tx];
    __syncthreads();
#pragma unroll
    for (int i = ty; i < 32; i += 8)
        dst[(size_t)(n0 + i) * K + k0 + tx] = __float2half_rn(t[tx][i]);
}

// ---------------- LayerNorm (emits fp16) -----------------------------------
__global__ void __launch_bounds__(256) ln_kernel(
    const float* __restrict__ x, const float* __restrict__ s,
    const float* __restrict__ b, __half* __restrict__ o)
{
    __shared__ float red[2][8];
    int row = blockIdx.x;
    const float* xr = x + (size_t)row * D_;
    __half* orow = o + (size_t)row * D_;
    int t = threadIdx.x;
    float v[4];
    float sum = 0.f, sq = 0.f;
#pragma unroll
    for (int i = 0; i < 4; i++) {
        float z = xr[t + i * 256];
        v[i] = z; sum += z; sq += z * z;
    }
#pragma unroll
    for (int off = 16; off > 0; off >>= 1) {
        sum += __shfl_xor_sync(0xffffffffu, sum, off);
        sq  += __shfl_xor_sync(0xffffffffu, sq,  off);
    }
    if ((t & 31) == 0) { red[0][t >> 5] = sum; red[1][t >> 5] = sq; }
    __syncthreads();
    sum = 0.f; sq = 0.f;
#pragma unroll
    for (int i = 0; i < 8; i++) { sum += red[0][i]; sq += red[1][i]; }
    float mean = sum * (1.f / D_);
    float var  = sq  * (1.f / D_) - mean * mean;
    float rstd = rsqrtf(var + 1e-5f);
#pragma unroll
    for (int i = 0; i < 4; i++) {
        int c = t + i * 256;
        orow[c] = __float2half_rn((v[i] - mean) * rstd * s[c] + b[c]);
    }
}

// ---------------- fp16 tensor-core GEMM, 3-stage cp.async, 2 CTAs/SM --------
// A: [M][K] fp16. Wt: [N][K] fp16. BM=128, BN=128, BK=64, 256 thr (8 warps,
// 4m x 2n, warp tile 32x64). One __syncthreads per k-iter.
// EPI bit0:+bias bit1:gelu bit2:+res.  OH: fp16 output.
// VT: V-columns (c >= 2*D) are written transposed into vt[bh][d][j] instead.
template<int EPI, int OH, int VT>
__global__ void __launch_bounds__(256, 2) gemm_hf(
    const __half* __restrict__ A, const __half* __restrict__ Wt,
    const float* __restrict__ bias, const float* __restrict__ res,
    void* __restrict__ Cv, __half* __restrict__ vt_, int M, int N, int K)
{
    const int MI = 2, NI = 8;            // WM=32, WN=64
    const int RS = 144;
    const int A_BYTES = 128 * RS;
    const int B_BYTES = 128 * RS;

    extern __shared__ char sm[];
    char* Asm = sm;
    char* Bsm = sm + 3 * A_BYTES;

    int tid = threadIdx.x;
    int bx = blockIdx.x, by = blockIdx.y;
    int wid = tid >> 5, lane = tid & 31;
    int wn = wid & 1, wm = wid >> 1;
    int g = lane >> 2, q = lane & 3;

    const __half* Ab = A  + (size_t)by * 128 * K;
    const __half* Bb = Wt + (size_t)bx * 128 * K;
    int KT = K / 64;

    float acc[MI][NI][4];
#pragma unroll
    for (int mi = 0; mi < MI; mi++)
#pragma unroll
        for (int ni = 0; ni < NI; ni++)
#pragma unroll
            for (int k = 0; k < 4; k++) acc[mi][ni][k] = 0.f;

    auto load_tile = [&](int kt, int s) {
#pragma unroll
        for (int i = 0; i < 4; i++) {
            int idx = tid + i * 256;
            int r = idx >> 3, c = idx & 7;
            cp16(Asm + s * A_BYTES + r * RS + c * 16,
                 Ab + (size_t)r * K + kt * 64 + c * 8);
        }
#pragma unroll
        for (int i = 0; i < 4; i++) {
            int idx = tid + i * 256;
            int r = idx >> 3, c = idx & 7;
            cp16(Bsm + s * B_BYTES + r * RS + c * 16,
                 Bb + (size_t)r * K + kt * 64 + c * 8);
        }
        cp_commit();
    };

    load_tile(0, 0);
    load_tile(1, 1);

    for (int kt = 0; kt < KT; kt++) {
        if (kt + 1 < KT) {
            asm volatile("cp.async.wait_group 1;");
        } else {
            asm volatile("cp.async.wait_group 0;");
        }
        __syncthreads();   // tile kt visible; buf (kt+2)%3 free
        if (kt + 2 < KT) load_tile(kt + 2, (kt + 2) % 3);
        int s = kt % 3;
        const char* As = Asm + s * A_BYTES;
        const char* Bs = Bsm + s * B_BYTES;
#pragma unroll
        for (int ks = 0; ks < 4; ks++) {
            int kb = ks * 32;
            uint32_t a[MI][4];
#pragma unroll
            for (int mi = 0; mi < MI; mi++) {
                const char* p0 = As + (wm * 32 + mi * 16 + g) * RS + kb + 4 * q;
                const char* p1 = As + (wm * 32 + mi * 16 + 8 + g) * RS + kb + 4 * q;
                a[mi][0] = *(const uint32_t*)(p0);
                a[mi][1] = *(const uint32_t*)(p1);
                a[mi][2] = *(const uint32_t*)(p0 + 16);
                a[mi][3] = *(const uint32_t*)(p1 + 16);
            }
            uint32_t b[NI][2];
#pragma unroll
            for (int ni = 0; ni < NI; ni++) {
                const char* pb = Bs + (wn * 64 + ni * 8 + g) * RS + kb + 4 * q;
                b[ni][0] = *(const uint32_t*)(pb);
                b[ni][1] = *(const uint32_t*)(pb + 16);
            }
#pragma unroll
            for (int mi = 0; mi < MI; mi++)
#pragma unroll
                for (int ni = 0; ni < NI; ni++) mma16(acc[mi][ni], a[mi], b[ni]);
        }
    }

#pragma unroll
    for (int mi = 0; mi < MI; mi++) {
        int r0 = by * 128 + wm * 32 + mi * 16 + g;
#pragma unroll
        for (int ni = 0; ni < NI; ni++) {
            int c = bx * 128 + wn * 64 + ni * 8 + q * 2;
            float2 v0 = make_float2(acc[mi][ni][0], acc[mi][ni][1]);
            float2 v1 = make_float2(acc[mi][ni][2], acc[mi][ni][3]);
            if (EPI & 1) {
                float b0 = bias[c], b1 = bias[c + 1];
                v0.x += b0; v0.y += b1; v1.x += b0; v1.y += b1;
            }
            if (EPI & 2) {
                const float is2 = 0.70710678118654752f;
                v0.x = 0.5f * v0.x * (1.f + erff(v0.x * is2));
                v0.y = 0.5f * v0.y * (1.f + erff(v0.y * is2));
                v1.x = 0.5f * v1.x * (1.f + erff(v1.x * is2));
                v1.y = 0.5f * v1.y * (1.f + erff(v1.y * is2));
            }
            if (VT && c >= 2 * D_) {
                // write V transposed: vt[(b*16+h)*64+d][n]
                int dall = c - 2 * D_;
                int hh = dall >> 6, dd = dall & 63;
                int bb = r0 >> 10, n0 = r0 & 1023;
                __half* vp = vt_ + (((size_t)(bb * H_ + hh) * DH_ + dd) << 10);
                vp[n0]            = __float2half_rn(v0.x);
                vp[1024 + n0]     = __float2half_rn(v0.y);
                vp[n0 + 8]        = __float2half_rn(v1.x);
                vp[1024 + n0 + 8] = __float2half_rn(v1.y);
                continue;
            }
            size_t a0 = (size_t)r0 * N + c;
            size_t a1 = (size_t)(r0 + 8) * N + c;
            if (EPI & 4) {
                float2 r0v = *(const float2*)(res + a0);
                float2 r1v = *(const float2*)(res + a1);
                v0.x += r0v.x; v0.y += r0v.y; v1.x += r1v.x; v1.y += r1v.y;
            }
            if (OH) {
                __half* C = (__half*)Cv;
                *(__half2*)(C + a0) = __floats2half2_rn(v0.x, v0.y);
                *(__half2*)(C + a1) = __floats2half2_rn(v1.x, v1.y);
            } else {
                float* C = (float*)Cv;
                *(float2*)(C + a0) = v0;
                *(float2*)(C + a1) = v1;
            }
        }
    }
}

// ---------------- fused flash attention (fp16, 3-stage, register-P) ---------
// grid (N/128 = 8, B*H = 32), 256 thr = 8 warps; warp w owns q-rows w*16..+15.
// P stays in registers: S's mma C-fragment layout equals PV's A-fragment layout.
// smem: Q 18K | K 3x9K | Vt 3x9K = 73728 -> 2 CTAs/SM.
#define FL_RS    144
#define FL_Q     0
#define FL_K     (128 * FL_RS)
#define FL_V     (FL_K + 3 * 64 * FL_RS)
#define FL_SMEM  (FL_V + 3 * 64 * FL_RS)    /* 73728 */

__global__ void __launch_bounds__(256, 2) flash_hf(
    const __half* __restrict__ qkv, const __half* __restrict__ vt,
    __half* __restrict__ o)
{
    const int RS = FL_RS;
    extern __shared__ char sm[];
    char* Qs = sm + FL_Q;
    char* Ks = sm + FL_K;
    char* Vs = sm + FL_V;

    int bh = blockIdx.y;
    int b = bh >> 4, h = bh & 15;
    int i0 = blockIdx.x * 128;
    const __half* Qb  = qkv + (size_t)b * N_ * 3 * D_ + (size_t)h * DH_;
    const __half* Kb  = Qb + D_;
    const __half* Vtb = vt + (size_t)bh * DH_ * N_;

    int tid = threadIdx.x, wid = tid >> 5, lane = tid & 31;
    int g = lane >> 2, q = lane & 3;

#pragma unroll
    for (int i = 0; i < 4; i++) {
        int idx = tid + i * 256;
        int r = idx >> 3, c = idx & 7;
        cp16(Qs + r * RS + c * 16, Qb + (size_t)(i0 + r) * 3 * D_ + c * 8);
    }
    cp_commit();

    auto load_kv = [&](int kt, int s) {
        int j0 = kt * 64;
#pragma unroll
        for (int i = 0; i < 2; i++) {
            int idx = tid + i * 256;
            int r = idx >> 3, c = idx & 7;
            cp16(Ks + s * 64 * RS + r * RS + c * 16,
                 Kb + (size_t)(j0 + r) * 3 * D_ + c * 8);
            cp16(Vs + s * 64 * RS + r * RS + c * 16,
                 Vtb + (size_t)r * N_ + j0 + c * 8);
        }
        cp_commit();
    };

    load_kv(0, 0);
    load_kv(1, 1);

    float oacc[8][4];
#pragma unroll
    for (int ni = 0; ni < 8; ni++)
#pragma unroll
        for (int k = 0; k < 4; k++) oacc[ni][k] = 0.f;
    float mr0 = -1e30f, mr1 = -1e30f, lr0 = 0.f, lr1 = 0.f;

    const float scale = 0.03125f;   // D^-0.5 (full-dim per reference)
    char* Qw = Qs + wid * 16 * RS;

    for (int kt = 0; kt < 16; kt++) {
        if (kt + 1 < 16) {
            asm volatile("cp.async.wait_group 1;");
        } else {
            asm volatile("cp.async.wait_group 0;");
        }
        __syncthreads();   // chunk kt (and Q) visible; buf (kt+2)%3 free
        if (kt + 2 < 16) load_kv(kt + 2, (kt + 2) % 3);
        int s = kt % 3;
        const char* Kc = Ks + s * 64 * RS;
        const char* Vc = Vs + s * 64 * RS;

        // ---- S = Q K^T (warp: 16 x 64) ----
        float sacc[8][4];
#pragma unroll
        for (int ni = 0; ni < 8; ni++)
#pragma unroll
            for (int k = 0; k < 4; k++) sacc[ni][k] = 0.f;
#pragma unroll
        for (int ks = 0; ks < 4; ks++) {
            int kb = ks * 32;
            uint32_t a[4];
            const char* p0 = Qw + g * RS + kb + 4 * q;
            const char* p1 = Qw + (8 + g) * RS + kb + 4 * q;
            a[0] = *(const uint32_t*)(p0);
            a[1] = *(const uint32_t*)(p1);
            a[2] = *(const uint32_t*)(p0 + 16);
            a[3] = *(const uint32_t*)(p1 + 16);
#pragma unroll
            for (int ni = 0; ni < 8; ni++) {
                uint32_t b2[2];
                const char* pb = Kc + (ni * 8 + g) * RS + kb + 4 * q;
                b2[0] = *(const uint32_t*)(pb);
                b2[1] = *(const uint32_t*)(pb + 16);
                mma16(sacc[ni], a, b2);
            }
        }

        // ---- online softmax (rows g, 8+g); sacc becomes exp(P) ----
        float mx0 = -1e30f, mx1 = -1e30f;
#pragma unroll
        for (int ni = 0; ni < 8; ni++) {
            sacc[ni][0] *= scale; sacc[ni][1] *= scale;
            sacc[ni][2] *= scale; sacc[ni][3] *= scale;
            mx0 = fmaxf(mx0, fmaxf(sacc[ni][0], sacc[ni][1]));
            mx1 = fmaxf(mx1, fmaxf(sacc[ni][2], sacc[ni][3]));
        }
        mx0 = fmaxf(mx0, __shfl_xor_sync(0xffffffffu, mx0, 1));
        mx0 = fmaxf(mx0, __shfl_xor_sync(0xffffffffu, mx0, 2));
        mx1 = fmaxf(mx1, __shfl_xor_sync(0xffffffffu, mx1, 1));
        mx1 = fmaxf(mx1, __shfl_xor_sync(0xffffffffu, mx1, 2));
        float mn0 = fmaxf(mr0, mx0), mn1 = fmaxf(mr1, mx1);
        float corr0 = __expf(mr0 - mn0), corr1 = __expf(mr1 - mn1);
        mr0 = mn0; mr1 = mn1;

        float ls0 = 0.f, ls1 = 0.f;
#pragma unroll
        for (int ni = 0; ni < 8; ni++) {
            sacc[ni][0] = __expf(sacc[ni][0] - mn0);
            sacc[ni][1] = __expf(sacc[ni][1] - mn0);
            sacc[ni][2] = __expf(sacc[ni][2] - mn1);
            sacc[ni][3] = __expf(sacc[ni][3] - mn1);
            ls0 += sacc[ni][0] + sacc[ni][1];
            ls1 += sacc[ni][2] + sacc[ni][3];
        }
        lr0 = lr0 * corr0 + ls0;
        lr1 = lr1 * corr1 + ls1;
#pragma unroll
        for (int ni = 0; ni < 8; ni++) {
            oacc[ni][0] *= corr0; oacc[ni][1] *= corr0;
            oacc[ni][2] *= corr1; oacc[ni][3] *= corr1;
        }

        // ---- O += P * Vt; P's A-fragment built in registers from sacc ----
#pragma unroll
        for (int t = 0; t < 4; t++) {
            uint32_t pa[4];
            pa[0] = pack2(sacc[2 * t][0],     sacc[2 * t][1]);
            pa[1] = pack2(sacc[2 * t][2],     sacc[2 * t][3]);
            pa[2] = pack2(sacc[2 * t + 1][0], sacc[2 * t + 1][1]);
            pa[3] = pack2(sacc[2 * t + 1][2], sacc[2 * t + 1][3]);
            int kb = t * 32;
#pragma unroll
            for (int ni = 0; ni < 8; ni++) {
                uint32_t b2[2];
                const char* pb = Vc + (ni * 8 + g) * RS + kb + 4 * q;
                b2[0] = *(const uint32_t*)(pb);
                b2[1] = *(const uint32_t*)(pb + 16);
                mma16(oacc[ni], pa, b2);
            }
        }
    }

    lr0 += __shfl_xor_sync(0xffffffffu, lr0, 1);
    lr0 += __shfl_xor_sync(0xffffffffu, lr0, 2);
    lr1 += __shfl_xor_sync(0xffffffffu, lr1, 1);
    lr1 += __shfl_xor_sync(0xffffffffu, lr1, 2);
    float inv0 = 1.f / lr0, inv1 = 1.f / lr1;

    int r0 = i0 + wid * 16 + g, r1 = r0 + 8;
#pragma unroll
    for (int ni = 0; ni < 8; ni++) {
        int c = h * DH_ + ni * 8 + q * 2;
        size_t a0 = ((size_t)b * N_ + r0) * D_ + c;
        size_t a1 = ((size_t)b * N_ + r1) * D_ + c;
        *(__half2*)(o + a0) = __floats2half2_rn(oacc[ni][0] * inv0, oacc[ni][1] * inv0);
        *(__half2*)(o + a1) = __floats2half2_rn(oacc[ni][2] * inv1, oacc[ni][3] * inv1);
    }
}

// ---------------- orchestration --------------------------------------------
#define HF_SMEM (3 * (128 * 144) + 3 * (128 * 144))   /* 110592 -> 2 CTAs/SM */

extern "C" void kernel_launch(void* const* d_in, const int* in_sizes, int n_in,
                              void* d_out, int out_size)
{
    (void)in_sizes; (void)n_in; (void)out_size;
    const float* x     = (const float*)d_in[0];
    const float* ln1_s = (const float*)d_in[1];
    const float* ln1_b = (const float*)d_in[2];
    const float* w_qkv = (const float*)d_in[3];
    const float* w_out = (const float*)d_in[4];
    const float* b_out = (const float*)d_in[5];
    const float* ln2_s = (const float*)d_in[6];
    const float* ln2_b = (const float*)d_in[7];
    const float* w1    = (const float*)d_in[8];
    const float* b1    = (const float*)d_in[9];
    const float* w2    = (const float*)d_in[10];
    const float* b2    = (const float*)d_in[11];
    float* out = (float*)d_out;

    __half *h, *qkv, *vt, *o, *mlp, *wqkv, *wout, *w1t, *w2t;
    cudaGetSymbolAddress((void**)&h,    g_h);
    cudaGetSymbolAddress((void**)&qkv,  g_qkv);
    cudaGetSymbolAddress((void**)&vt,   g_vt);
    cudaGetSymbolAddress((void**)&o,    g_o);
    cudaGetSymbolAddress((void**)&mlp,  g_mlp);
    cudaGetSymbolAddress((void**)&wqkv, g_wqkv);
    cudaGetSymbolAddress((void**)&wout, g_wout);
    cudaGetSymbolAddress((void**)&w1t,  g_w1);
    cudaGetSymbolAddress((void**)&w2t,  g_w2);

    cudaFuncSetAttribute(gemm_hf<0, 1, 1>,
        cudaFuncAttributeMaxDynamicSharedMemorySize, HF_SMEM);
    cudaFuncSetAttribute(gemm_hf<3, 1, 0>,
        cudaFuncAttributeMaxDynamicSharedMemorySize, HF_SMEM);
    cudaFuncSetAttribute(gemm_hf<5, 0, 0>,
        cudaFuncAttributeMaxDynamicSharedMemorySize, HF_SMEM);
    cudaFuncSetAttribute(flash_hf,
        cudaFuncAttributeMaxDynamicSharedMemorySize, FL_SMEM);

    // pre-pass: weights -> [N][K] fp16
    wtrans_kernel<<<dim3(3 * D_ / 32, D_ / 32, DEPTH_), 256>>>(w_qkv, wqkv, D_, 3 * D_);
    wtrans_kernel<<<dim3(D_ / 32, D_ / 32, DEPTH_), 256>>>(w_out, wout, D_, D_);
    wtrans_kernel<<<dim3(MLP_ / 32, D_ / 32, DEPTH_), 256>>>(w1, w1t, D_, MLP_);
    wtrans_kernel<<<dim3(D_ / 32, MLP_ / 32, DEPTH_), 256>>>(w2, w2t, MLP_, D_);

    cudaMemcpyAsync(out, x, (size_t)M_ * D_ * sizeof(float),
                    cudaMemcpyDeviceToDevice);

    for (int l = 0; l < DEPTH_; l++) {
        // --- attention block ---
        ln_kernel<<<M_, 256>>>(out, ln1_s + (size_t)l * D_, ln1_b + (size_t)l * D_, h);
        gemm_hf<0, 1, 1><<<dim3(3 * D_ / 128, M_ / 128), 256, HF_SMEM>>>(
            h, wqkv + (size_t)l * D_ * 3 * D_, nullptr, nullptr,
            qkv, vt, M_, 3 * D_, D_);
        flash_hf<<<dim3(N_ / 128, B_ * H_), 256, FL_SMEM>>>(qkv, vt, o);
        gemm_hf<5, 0, 0><<<dim3(D_ / 128, M_ / 128), 256, HF_SMEM>>>(
            o, wout + (size_t)l * D_ * D_, b_out + (size_t)l * D_,
            out, out, nullptr, M_, D_, D_);
        // --- MLP block ---
        ln_kernel<<<M_, 256>>>(out, ln2_s + (size_t)l * D_, ln2_b + (size_t)l * D_, h);
        gemm_hf<3, 1, 0><<<dim3(MLP_ / 128, M_ / 128), 256, HF_SMEM>>>(
            h, w1t + (size_t)l * D_ * MLP_, b1 + (size_t)l * MLP_,
            nullptr, mlp, nullptr, M_, MLP_, D_);
        gemm_hf<5, 0, 0><<<dim3(D_ / 128, M_ / 128), 256, HF_SMEM>>>(
            mlp, w2t + (size_t)l * MLP_ * D_, b2 + (size_t)l * D_,
            out, out, nullptr, M_, D_, MLP_);
    }
}

// round 17
// speedup vs baseline: 1.1206x; 1.0086x over previous
#include <cuda_runtime.h>
#include <cuda_fp16.h>
#include <math.h>
#include <stdint.h>

#define B_    2
#define N_    1024
#define D_    1024
#define H_    16
#define DH_   64
#define MLP_  4096
#define DEPTH_ 6
#define M_    (B_ * N_)   /* 2048 rows */

// ---------------- scratch -----------------------------------------------
__device__ __half g_h  [(size_t)M_ * D_];
__device__ __half g_qkv[(size_t)M_ * 3 * D_];
__device__ __half g_vt [(size_t)B_ * H_ * DH_ * N_];
__device__ __half g_o  [(size_t)M_ * D_];
__device__ __half g_mlp[(size_t)M_ * MLP_];
__device__ __half g_wqkv[(size_t)DEPTH_ * D_ * 3 * D_];
__device__ __half g_wout[(size_t)DEPTH_ * D_ * D_];
__device__ __half g_w1  [(size_t)DEPTH_ * D_ * MLP_];
__device__ __half g_w2  [(size_t)DEPTH_ * MLP_ * D_];

// ---------------- helpers ---------------------------------------------------
__device__ __forceinline__ void mma16(float* d, const uint32_t* a, const uint32_t* b) {
    asm volatile(
        "mma.sync.aligned.m16n8k16.row.col.f32.f16.f16.f32 "
        "{%0,%1,%2,%3},{%4,%5,%6,%7},{%8,%9},{%0,%1,%2,%3};"
        : "+f"(d[0]), "+f"(d[1]), "+f"(d[2]), "+f"(d[3])
        : "r"(a[0]), "r"(a[1]), "r"(a[2]), "r"(a[3]),
          "r"(b[0]), "r"(b[1]));
}
__device__ __forceinline__ uint32_t pack2(float x, float y) {
    __half2 h = __floats2half2_rn(x, y);
    return *(uint32_t*)&h;
}
__device__ __forceinline__ void cp16(void* smem_dst, const void* gmem_src) {
    uint32_t dst = (uint32_t)__cvta_generic_to_shared(smem_dst);
    asm volatile("cp.async.cg.shared.global [%0], [%1], 16;"
                 :: "r"(dst), "l"(gmem_src));
}
__device__ __forceinline__ void cp_commit() {
    asm volatile("cp.async.commit_group;");
}

// ---------------- weight pre-pass: [K,N] fp32 -> [N,K] fp16 -----------------
// Tile: 64 k x 32 n. Smem staged [n][k] (conflict-free stores, aligned float2
// reads). Output rows written as coalesced half2 (128B per warp).
__global__ void __launch_bounds__(256) wtrans_kernel(
    const float* __restrict__ src, __half* __restrict__ dst, int K, int N)
{
    __shared__ float t[32][66];
    int n0 = blockIdx.x * 32, k0 = blockIdx.y * 64;
    src += (size_t)blockIdx.z * K * N;
    dst += (size_t)blockIdx.z * K * N;
    int tx = threadIdx.x & 31, ty = threadIdx.x >> 5;
#pragma unroll
    for (int i = ty; i < 64; i += 8)
        t[tx][i] = src[(size_t)(k0 + i) * N + n0 + tx];
    __syncthreads();
#pragma unroll
    for (int i = 0; i < 4; i++) {
        int w = threadIdx.x + i * 256;          // 0..1023
        int n = w >> 5, k2 = w & 31;
        float2 f = *(const float2*)&t[n][2 * k2];
        *(__half2*)(dst + (size_t)(n0 + n) * K + k0 + 2 * k2) =
            __floats2half2_rn(f.x, f.y);
    }
}

// ---------------- LayerNorm (emits fp16) -----------------------------------
__global__ void __launch_bounds__(256) ln_kernel(
    const float* __restrict__ x, const float* __restrict__ s,
    const float* __restrict__ b, __half* __restrict__ o)
{
    __shared__ float red[2][8];
    int row = blockIdx.x;
    const float* xr = x + (size_t)row * D_;
    __half* orow = o + (size_t)row * D_;
    int t = threadIdx.x;
    float v[4];
    float sum = 0.f, sq = 0.f;
#pragma unroll
    for (int i = 0; i < 4; i++) {
        float z = xr[t + i * 256];
        v[i] = z; sum += z; sq += z * z;
    }
#pragma unroll
    for (int off = 16; off > 0; off >>= 1) {
        sum += __shfl_xor_sync(0xffffffffu, sum, off);
        sq  += __shfl_xor_sync(0xffffffffu, sq,  off);
    }
    if ((t & 31) == 0) { red[0][t >> 5] = sum; red[1][t >> 5] = sq; }
    __syncthreads();
    sum = 0.f; sq = 0.f;
#pragma unroll
    for (int i = 0; i < 8; i++) { sum += red[0][i]; sq += red[1][i]; }
    float mean = sum * (1.f / D_);
    float var  = sq  * (1.f / D_) - mean * mean;
    float rstd = rsqrtf(var + 1e-5f);
#pragma unroll
    for (int i = 0; i < 4; i++) {
        int c = t + i * 256;
        orow[c] = __float2half_rn((v[i] - mean) * rstd * s[c] + b[c]);
    }
}

// ---------------- fp16 tensor-core GEMM, 3-stage cp.async, 2 CTAs/SM --------
// EPI bit0:+bias bit1:gelu bit2:+res.  OH: fp16 output.
// VT: QKV mode — Q columns (c < D) pre-scaled by D^-0.5 (exact, power of 2);
//     V columns (c >= 2D) written transposed into vt[bh][d][j].
template<int EPI, int OH, int VT>
__global__ void __launch_bounds__(256, 2) gemm_hf(
    const __half* __restrict__ A, const __half* __restrict__ Wt,
    const float* __restrict__ bias, const float* __restrict__ res,
    void* __restrict__ Cv, __half* __restrict__ vt_, int M, int N, int K)
{
    const int MI = 2, NI = 8;            // WM=32, WN=64
    const int RS = 144;
    const int A_BYTES = 128 * RS;
    const int B_BYTES = 128 * RS;

    extern __shared__ char sm[];
    char* Asm = sm;
    char* Bsm = sm + 3 * A_BYTES;

    int tid = threadIdx.x;
    int bx = blockIdx.x, by = blockIdx.y;
    int wid = tid >> 5, lane = tid & 31;
    int wn = wid & 1, wm = wid >> 1;
    int g = lane >> 2, q = lane & 3;

    const __half* Ab = A  + (size_t)by * 128 * K;
    const __half* Bb = Wt + (size_t)bx * 128 * K;
    int KT = K / 64;

    float acc[MI][NI][4];
#pragma unroll
    for (int mi = 0; mi < MI; mi++)
#pragma unroll
        for (int ni = 0; ni < NI; ni++)
#pragma unroll
            for (int k = 0; k < 4; k++) acc[mi][ni][k] = 0.f;

    auto load_tile = [&](int kt, int s) {
#pragma unroll
        for (int i = 0; i < 4; i++) {
            int idx = tid + i * 256;
            int r = idx >> 3, c = idx & 7;
            cp16(Asm + s * A_BYTES + r * RS + c * 16,
                 Ab + (size_t)r * K + kt * 64 + c * 8);
        }
#pragma unroll
        for (int i = 0; i < 4; i++) {
            int idx = tid + i * 256;
            int r = idx >> 3, c = idx & 7;
            cp16(Bsm + s * B_BYTES + r * RS + c * 16,
                 Bb + (size_t)r * K + kt * 64 + c * 8);
        }
        cp_commit();
    };

    load_tile(0, 0);
    load_tile(1, 1);

    for (int kt = 0; kt < KT; kt++) {
        if (kt + 1 < KT) {
            asm volatile("cp.async.wait_group 1;");
        } else {
            asm volatile("cp.async.wait_group 0;");
        }
        __syncthreads();   // tile kt visible; buf (kt+2)%3 free
        if (kt + 2 < KT) load_tile(kt + 2, (kt + 2) % 3);
        int s = kt % 3;
        const char* As = Asm + s * A_BYTES;
        const char* Bs = Bsm + s * B_BYTES;
#pragma unroll
        for (int ks = 0; ks < 4; ks++) {
            int kb = ks * 32;
            uint32_t a[MI][4];
#pragma unroll
            for (int mi = 0; mi < MI; mi++) {
                const char* p0 = As + (wm * 32 + mi * 16 + g) * RS + kb + 4 * q;
                const char* p1 = As + (wm * 32 + mi * 16 + 8 + g) * RS + kb + 4 * q;
                a[mi][0] = *(const uint32_t*)(p0);
                a[mi][1] = *(const uint32_t*)(p1);
                a[mi][2] = *(const uint32_t*)(p0 + 16);
                a[mi][3] = *(const uint32_t*)(p1 + 16);
            }
            uint32_t b[NI][2];
#pragma unroll
            for (int ni = 0; ni < NI; ni++) {
                const char* pb = Bs + (wn * 64 + ni * 8 + g) * RS + kb + 4 * q;
                b[ni][0] = *(const uint32_t*)(pb);
                b[ni][1] = *(const uint32_t*)(pb + 16);
            }
#pragma unroll
            for (int mi = 0; mi < MI; mi++)
#pragma unroll
                for (int ni = 0; ni < NI; ni++) mma16(acc[mi][ni], a[mi], b[ni]);
        }
    }

#pragma unroll
    for (int mi = 0; mi < MI; mi++) {
        int r0 = by * 128 + wm * 32 + mi * 16 + g;
#pragma unroll
        for (int ni = 0; ni < NI; ni++) {
            int c = bx * 128 + wn * 64 + ni * 8 + q * 2;
            float2 v0 = make_float2(acc[mi][ni][0], acc[mi][ni][1]);
            float2 v1 = make_float2(acc[mi][ni][2], acc[mi][ni][3]);
            if (EPI & 1) {
                float b0 = bias[c], b1 = bias[c + 1];
                v0.x += b0; v0.y += b1; v1.x += b0; v1.y += b1;
            }
            if (EPI & 2) {
                const float is2 = 0.70710678118654752f;
                v0.x = 0.5f * v0.x * (1.f + erff(v0.x * is2));
                v0.y = 0.5f * v0.y * (1.f + erff(v0.y * is2));
                v1.x = 0.5f * v1.x * (1.f + erff(v1.x * is2));
                v1.y = 0.5f * v1.y * (1.f + erff(v1.y * is2));
            }
            if (VT) {
                if (c < D_) {               // Q: pre-scale by D^-0.5 (exact)
                    v0.x *= 0.03125f; v0.y *= 0.03125f;
                    v1.x *= 0.03125f; v1.y *= 0.03125f;
                } else if (c >= 2 * D_) {   // V: write transposed into vt
                    int dall = c - 2 * D_;
                    int hh = dall >> 6, dd = dall & 63;
                    int bb = r0 >> 10, n0 = r0 & 1023;
                    __half* vp = vt_ + (((size_t)(bb * H_ + hh) * DH_ + dd) << 10);
                    vp[n0]            = __float2half_rn(v0.x);
                    vp[1024 + n0]     = __float2half_rn(v0.y);
                    vp[n0 + 8]        = __float2half_rn(v1.x);
                    vp[1024 + n0 + 8] = __float2half_rn(v1.y);
                    continue;
                }
            }
            size_t a0 = (size_t)r0 * N + c;
            size_t a1 = (size_t)(r0 + 8) * N + c;
            if (EPI & 4) {
                float2 r0v = *(const float2*)(res + a0);
                float2 r1v = *(const float2*)(res + a1);
                v0.x += r0v.x; v0.y += r0v.y; v1.x += r1v.x; v1.y += r1v.y;
            }
            if (OH) {
                __half* C = (__half*)Cv;
                *(__half2*)(C + a0) = __floats2half2_rn(v0.x, v0.y);
                *(__half2*)(C + a1) = __floats2half2_rn(v1.x, v1.y);
            } else {
                float* C = (float*)Cv;
                *(float2*)(C + a0) = v0;
                *(float2*)(C + a1) = v1;
            }
        }
    }
}

// ---------------- fused flash attention (fp16, 3-stage, register-P) ---------
// Q is pre-scaled by D^-0.5 (QKV epilogue), so S needs no scale here.
#define FL_RS    144
#define FL_Q     0
#define FL_K     (128 * FL_RS)
#define FL_V     (FL_K + 3 * 64 * FL_RS)
#define FL_SMEM  (FL_V + 3 * 64 * FL_RS)    /* 73728 */

__global__ void __launch_bounds__(256, 2) flash_hf(
    const __half* __restrict__ qkv, const __half* __restrict__ vt,
    __half* __restrict__ o)
{
    const int RS = FL_RS;
    extern __shared__ char sm[];
    char* Qs = sm + FL_Q;
    char* Ks = sm + FL_K;
    char* Vs = sm + FL_V;

    int bh = blockIdx.y;
    int b = bh >> 4, h = bh & 15;
    int i0 = blockIdx.x * 128;
    const __half* Qb  = qkv + (size_t)b * N_ * 3 * D_ + (size_t)h * DH_;
    const __half* Kb  = Qb + D_;
    const __half* Vtb = vt + (size_t)bh * DH_ * N_;

    int tid = threadIdx.x, wid = tid >> 5, lane = tid & 31;
    int g = lane >> 2, q = lane & 3;

#pragma unroll
    for (int i = 0; i < 4; i++) {
        int idx = tid + i * 256;
        int r = idx >> 3, c = idx & 7;
        cp16(Qs + r * RS + c * 16, Qb + (size_t)(i0 + r) * 3 * D_ + c * 8);
    }
    cp_commit();

    auto load_kv = [&](int kt, int s) {
        int j0 = kt * 64;
#pragma unroll
        for (int i = 0; i < 2; i++) {
            int idx = tid + i * 256;
            int r = idx >> 3, c = idx & 7;
            cp16(Ks + s * 64 * RS + r * RS + c * 16,
                 Kb + (size_t)(j0 + r) * 3 * D_ + c * 8);
            cp16(Vs + s * 64 * RS + r * RS + c * 16,
                 Vtb + (size_t)r * N_ + j0 + c * 8);
        }
        cp_commit();
    };

    load_kv(0, 0);
    load_kv(1, 1);

    float oacc[8][4];
#pragma unroll
    for (int ni = 0; ni < 8; ni++)
#pragma unroll
        for (int k = 0; k < 4; k++) oacc[ni][k] = 0.f;
    float mr0 = -1e30f, mr1 = -1e30f, lr0 = 0.f, lr1 = 0.f;

    char* Qw = Qs + wid * 16 * RS;

    for (int kt = 0; kt < 16; kt++) {
        if (kt + 1 < 16) {
            asm volatile("cp.async.wait_group 1;");
        } else {
            asm volatile("cp.async.wait_group 0;");
        }
        __syncthreads();   // chunk kt (and Q) visible; buf (kt+2)%3 free
        if (kt + 2 < 16) load_kv(kt + 2, (kt + 2) % 3);
        int s = kt % 3;
        const char* Kc = Ks + s * 64 * RS;
        const char* Vc = Vs + s * 64 * RS;

        // ---- S = Q K^T (warp: 16 x 64); Q already carries the scale ----
        float sacc[8][4];
#pragma unroll
        for (int ni = 0; ni < 8; ni++)
#pragma unroll
            for (int k = 0; k < 4; k++) sacc[ni][k] = 0.f;
#pragma unroll
        for (int ks = 0; ks < 4; ks++) {
            int kb = ks * 32;
            uint32_t a[4];
            const char* p0 = Qw + g * RS + kb + 4 * q;
            const char* p1 = Qw + (8 + g) * RS + kb + 4 * q;
            a[0] = *(const uint32_t*)(p0);
            a[1] = *(const uint32_t*)(p1);
            a[2] = *(const uint32_t*)(p0 + 16);
            a[3] = *(const uint32_t*)(p1 + 16);
#pragma unroll
            for (int ni = 0; ni < 8; ni++) {
                uint32_t b2[2];
                const char* pb = Kc + (ni * 8 + g) * RS + kb + 4 * q;
                b2[0] = *(const uint32_t*)(pb);
                b2[1] = *(const uint32_t*)(pb + 16);
                mma16(sacc[ni], a, b2);
            }
        }

        // ---- online softmax (rows g, 8+g); sacc becomes exp(P) ----
        float mx0 = -1e30f, mx1 = -1e30f;
#pragma unroll
        for (int ni = 0; ni < 8; ni++) {
            mx0 = fmaxf(mx0, fmaxf(sacc[ni][0], sacc[ni][1]));
            mx1 = fmaxf(mx1, fmaxf(sacc[ni][2], sacc[ni][3]));
        }
        mx0 = fmaxf(mx0, __shfl_xor_sync(0xffffffffu, mx0, 1));
        mx0 = fmaxf(mx0, __shfl_xor_sync(0xffffffffu, mx0, 2));
        mx1 = fmaxf(mx1, __shfl_xor_sync(0xffffffffu, mx1, 1));
        mx1 = fmaxf(mx1, __shfl_xor_sync(0xffffffffu, mx1, 2));
        float mn0 = fmaxf(mr0, mx0), mn1 = fmaxf(mr1, mx1);
        float corr0 = __expf(mr0 - mn0), corr1 = __expf(mr1 - mn1);
        mr0 = mn0; mr1 = mn1;

        float ls0 = 0.f, ls1 = 0.f;
#pragma unroll
        for (int ni = 0; ni < 8; ni++) {
            sacc[ni][0] = __expf(sacc[ni][0] - mn0);
            sacc[ni][1] = __expf(sacc[ni][1] - mn0);
            sacc[ni][2] = __expf(sacc[ni][2] - mn1);
            sacc[ni][3] = __expf(sacc[ni][3] - mn1);
            ls0 += sacc[ni][0] + sacc[ni][1];
            ls1 += sacc[ni][2] + sacc[ni][3];
        }
        lr0 = lr0 * corr0 + ls0;
        lr1 = lr1 * corr1 + ls1;
#pragma unroll
        for (int ni = 0; ni < 8; ni++) {
            oacc[ni][0] *= corr0; oacc[ni][1] *= corr0;
            oacc[ni][2] *= corr1; oacc[ni][3] *= corr1;
        }

        // ---- O += P * Vt; P's A-fragment built in registers from sacc ----
#pragma unroll
        for (int t = 0; t < 4; t++) {
            uint32_t pa[4];
            pa[0] = pack2(sacc[2 * t][0],     sacc[2 * t][1]);
            pa[1] = pack2(sacc[2 * t][2],     sacc[2 * t][3]);
            pa[2] = pack2(sacc[2 * t + 1][0], sacc[2 * t + 1][1]);
            pa[3] = pack2(sacc[2 * t + 1][2], sacc[2 * t + 1][3]);
            int kb = t * 32;
#pragma unroll
            for (int ni = 0; ni < 8; ni++) {
                uint32_t b2[2];
                const char* pb = Vc + (ni * 8 + g) * RS + kb + 4 * q;
                b2[0] = *(const uint32_t*)(pb);
                b2[1] = *(const uint32_t*)(pb + 16);
                mma16(oacc[ni], pa, b2);
            }
        }
    }

    lr0 += __shfl_xor_sync(0xffffffffu, lr0, 1);
    lr0 += __shfl_xor_sync(0xffffffffu, lr0, 2);
    lr1 += __shfl_xor_sync(0xffffffffu, lr1, 1);
    lr1 += __shfl_xor_sync(0xffffffffu, lr1, 2);
    float inv0 = 1.f / lr0, inv1 = 1.f / lr1;

    int r0 = i0 + wid * 16 + g, r1 = r0 + 8;
#pragma unroll
    for (int ni = 0; ni < 8; ni++) {
        int c = h * DH_ + ni * 8 + q * 2;
        size_t a0 = ((size_t)b * N_ + r0) * D_ + c;
        size_t a1 = ((size_t)b * N_ + r1) * D_ + c;
        *(__half2*)(o + a0) = __floats2half2_rn(oacc[ni][0] * inv0, oacc[ni][1] * inv0);
        *(__half2*)(o + a1) = __floats2half2_rn(oacc[ni][2] * inv1, oacc[ni][3] * inv1);
    }
}

// ---------------- orchestration --------------------------------------------
#define HF_SMEM (3 * (128 * 144) + 3 * (128 * 144))   /* 110592 -> 2 CTAs/SM */

extern "C" void kernel_launch(void* const* d_in, const int* in_sizes, int n_in,
                              void* d_out, int out_size)
{
    (void)in_sizes; (void)n_in; (void)out_size;
    const float* x     = (const float*)d_in[0];
    const float* ln1_s = (const float*)d_in[1];
    const float* ln1_b = (const float*)d_in[2];
    const float* w_qkv = (const float*)d_in[3];
    const float* w_out = (const float*)d_in[4];
    const float* b_out = (const float*)d_in[5];
    const float* ln2_s = (const float*)d_in[6];
    const float* ln2_b = (const float*)d_in[7];
    const float* w1    = (const float*)d_in[8];
    const float* b1    = (const float*)d_in[9];
    const float* w2    = (const float*)d_in[10];
    const float* b2    = (const float*)d_in[11];
    float* out = (float*)d_out;

    __half *h, *qkv, *vt, *o, *mlp, *wqkv, *wout, *w1t, *w2t;
    cudaGetSymbolAddress((void**)&h,    g_h);
    cudaGetSymbolAddress((void**)&qkv,  g_qkv);
    cudaGetSymbolAddress((void**)&vt,   g_vt);
    cudaGetSymbolAddress((void**)&o,    g_o);
    cudaGetSymbolAddress((void**)&mlp,  g_mlp);
    cudaGetSymbolAddress((void**)&wqkv, g_wqkv);
    cudaGetSymbolAddress((void**)&wout, g_wout);
    cudaGetSymbolAddress((void**)&w1t,  g_w1);
    cudaGetSymbolAddress((void**)&w2t,  g_w2);

    cudaFuncSetAttribute(gemm_hf<0, 1, 1>,
        cudaFuncAttributeMaxDynamicSharedMemorySize, HF_SMEM);
    cudaFuncSetAttribute(gemm_hf<3, 1, 0>,
        cudaFuncAttributeMaxDynamicSharedMemorySize, HF_SMEM);
    cudaFuncSetAttribute(gemm_hf<5, 0, 0>,
        cudaFuncAttributeMaxDynamicSharedMemorySize, HF_SMEM);
    cudaFuncSetAttribute(flash_hf,
        cudaFuncAttributeMaxDynamicSharedMemorySize, FL_SMEM);

    // pre-pass: weights -> [N][K] fp16 (coalesced half2 writes)
    wtrans_kernel<<<dim3(3 * D_ / 32, D_ / 64, DEPTH_), 256>>>(w_qkv, wqkv, D_, 3 * D_);
    wtrans_kernel<<<dim3(D_ / 32, D_ / 64, DEPTH_), 256>>>(w_out, wout, D_, D_);
    wtrans_kernel<<<dim3(MLP_ / 32, D_ / 64, DEPTH_), 256>>>(w1, w1t, D_, MLP_);
    wtrans_kernel<<<dim3(D_ / 32, MLP_ / 64, DEPTH_), 256>>>(w2, w2t, MLP_, D_);

    cudaMemcpyAsync(out, x, (size_t)M_ * D_ * sizeof(float),
                    cudaMemcpyDeviceToDevice);

    for (int l = 0; l < DEPTH_; l++) {
        // --- attention block ---
        ln_kernel<<<M_, 256>>>(out, ln1_s + (size_t)l * D_, ln1_b + (size_t)l * D_, h);
        gemm_hf<0, 1, 1><<<dim3(3 * D_ / 128, M_ / 128), 256, HF_SMEM>>>(
            h, wqkv + (size_t)l * D_ * 3 * D_, nullptr, nullptr,
            qkv, vt, M_, 3 * D_, D_);
        flash_hf<<<dim3(N_ / 128, B_ * H_), 256, FL_SMEM>>>(qkv, vt, o);
        gemm_hf<5, 0, 0><<<dim3(D_ / 128, M_ / 128), 256, HF_SMEM>>>(
            o, wout + (size_t)l * D_ * D_, b_out + (size_t)l * D_,
            out, out, nullptr, M_, D_, D_);
        // --- MLP block ---
        ln_kernel<<<M_, 256>>>(out, ln2_s + (size_t)l * D_, ln2_b + (size_t)l * D_, h);
        gemm_hf<3, 1, 0><<<dim3(MLP_ / 128, M_ / 128), 256, HF_SMEM>>>(
            h, w1t + (size_t)l * D_ * MLP_, b1 + (size_t)l * MLP_,
            nullptr, mlp, nullptr, M_, MLP_, D_);
        gemm_hf<5, 0, 0><<<dim3(D_ / 128, M_ / 128), 256, HF_SMEM>>>(
            mlp, w2t + (size_t)l * MLP_ * D_, b2 + (size_t)l * D_,
            out, out, nullptr, M_, D_, MLP_);
    }
}